// round 6
// baseline (speedup 1.0000x reference)
#include <cuda_runtime.h>
#include <cstdint>

// Problem constants
#define T_TOK 4096      // B*S
#define HDIM  1024
#define HFF   4096
#define NEXP  8
#define KTOP  2

// GEMM tiling
#define BM 128
#define BN 128
#define BKT 16
#define NTHREADS 256

// ---------------- device scratch (static: no allocations allowed) ----------
__device__ int   g_cnt[NEXP];
__device__ int   g_base[NEXP];
__device__ int   g_list[NEXP * T_TOK];
__device__ float g_gval[NEXP * T_TOK];
__device__ int   g_i32flag;
// H buffer: one row per (expert, slot) entry; padded by BM rows so tail tiles
// of the LAST expert can be read (never written) without OOB.
__device__ float g_hbuf[(size_t)(T_TOK * KTOP + BM) * HFF];

// ---------------- helpers --------------------------------------------------
__device__ __forceinline__ float tf32r(float x) {
    uint32_t o;
    asm("cvt.rna.tf32.f32 %0, %1;" : "=r"(o) : "f"(x));
    return __uint_as_float(o);
}

__device__ __forceinline__ float gelu_tanh(float x) {
    // jax.nn.gelu default: approximate=True (tanh form)
    float x3 = x * x * x;
    float t = tanhf(0.7978845608028654f * (x + 0.044715f * x3));
    return 0.5f * x * (1.0f + t);
}

#define MMA_TF32(c, a, b)                                                   \
    asm volatile(                                                           \
        "mma.sync.aligned.m16n8k8.row.col.f32.tf32.tf32.f32 "               \
        "{%0,%1,%2,%3}, {%4,%5,%6,%7}, {%8,%9}, {%0,%1,%2,%3};"             \
        : "+f"((c)[0]), "+f"((c)[1]), "+f"((c)[2]), "+f"((c)[3])            \
        : "r"((a)[0]), "r"((a)[1]), "r"((a)[2]), "r"((a)[3]),               \
          "r"((b)[0]), "r"((b)[1]))

// ---------------- small kernels --------------------------------------------
__global__ void k_zero(float4* out4, int n4) {
    int i = blockIdx.x * blockDim.x + threadIdx.x;
    if (i < n4) out4[i] = make_float4(0.f, 0.f, 0.f, 0.f);
    if (i < NEXP) g_cnt[i] = 0;
    if (i == 0) g_i32flag = 0;
}

// topk_indices may be int64 (x64 on) or int32 (default jax). Values are 0..7,
// so with int64 every odd int32 word is 0. Scan only the first T*K int32
// words (in-bounds for BOTH dtypes): any nonzero odd word => int32 data.
__global__ void k_detect(const int* __restrict__ idx32) {
    int i = blockIdx.x * blockDim.x + threadIdx.x;
    int v = 0;
    for (int j = i; j < (T_TOK * KTOP) / 2; j += gridDim.x * blockDim.x)
        v |= idx32[2 * j + 1];
    if (v) atomicOr(&g_i32flag, 1);
}

__global__ void k_gate(const void* __restrict__ idx_raw,
                       const float* __restrict__ probs) {
    int t = blockIdx.x * blockDim.x + threadIdx.x;
    if (t >= T_TOK) return;
    int e0, e1;
    if (g_i32flag) {
        const int* p = (const int*)idx_raw;
        e0 = p[2 * t]; e1 = p[2 * t + 1];
    } else {
        const long long* p = (const long long*)idx_raw;
        e0 = (int)p[2 * t]; e1 = (int)p[2 * t + 1];
    }
    float p0 = probs[2 * t], p1 = probs[2 * t + 1];
    if (e0 == e1) { p0 = fmaxf(p0, p1); e1 = -1; }  // max over k dedups
    if ((unsigned)e0 < NEXP) {
        int pos = atomicAdd(&g_cnt[e0], 1);
        g_list[e0 * T_TOK + pos] = t;
        g_gval[e0 * T_TOK + pos] = p0;
    }
    if ((unsigned)e1 < NEXP) {
        int pos = atomicAdd(&g_cnt[e1], 1);
        g_list[e1 * T_TOK + pos] = t;
        g_gval[e1 * T_TOK + pos] = p1;
    }
}

__global__ void k_prefix() {
    int s = 0;
    for (int e = 0; e < NEXP; ++e) { g_base[e] = s; s += g_cnt[e]; }
}

// ---------------- GEMM mainloop shared pieces (macros for two kernels) -----
// Smem layout: [stage][k][row+pad]  — fragment loads are bank-conflict-free.

#define GEMM_PROLOG()                                                        \
    const int tid = threadIdx.x;                                             \
    const int lane = tid & 31, warp = tid >> 5;                              \
    const int wm = warp & 1, wn = warp >> 1;                                 \
    const int g = lane >> 2, tq = lane & 3;                                  \
    float acc[4][4][4];                                                      \
    _Pragma("unroll") for (int mi = 0; mi < 4; ++mi)                         \
    _Pragma("unroll") for (int ni = 0; ni < 4; ++ni)                         \
    _Pragma("unroll") for (int ci = 0; ci < 4; ++ci) acc[mi][ni][ci] = 0.f;

#define STS_STAGE(s)                                                         \
    do {                                                                     \
        _Pragma("unroll") for (int i = 0; i < 2; ++i) {                      \
            As[s][ac[i] + 0][ar[i]] = tf32r(fa[i].x);                        \
            As[s][ac[i] + 1][ar[i]] = tf32r(fa[i].y);                        \
            As[s][ac[i] + 2][ar[i]] = tf32r(fa[i].z);                        \
            As[s][ac[i] + 3][ar[i]] = tf32r(fa[i].w);                        \
            Bs[s][ac[i] + 0][ar[i]] = tf32r(fb[i].x);                        \
            Bs[s][ac[i] + 1][ar[i]] = tf32r(fb[i].y);                        \
            Bs[s][ac[i] + 2][ar[i]] = tf32r(fb[i].z);                        \
            Bs[s][ac[i] + 3][ar[i]] = tf32r(fb[i].w);                        \
        }                                                                    \
    } while (0)

#define COMPUTE_STAGE(cur)                                                   \
    do {                                                                     \
        _Pragma("unroll") for (int ks = 0; ks < 2; ++ks) {                   \
            const int kb = ks * 8;                                           \
            uint32_t aF[4][4], bF[4][2];                                     \
            _Pragma("unroll") for (int mi = 0; mi < 4; ++mi) {               \
                int rb = wm * 64 + mi * 16;                                  \
                aF[mi][0] = __float_as_uint(As[cur][kb + tq][rb + g]);       \
                aF[mi][1] = __float_as_uint(As[cur][kb + tq][rb + g + 8]);   \
                aF[mi][2] = __float_as_uint(As[cur][kb + tq + 4][rb + g]);   \
                aF[mi][3] = __float_as_uint(As[cur][kb + tq + 4][rb + g + 8]);\
            }                                                                \
            _Pragma("unroll") for (int ni = 0; ni < 4; ++ni) {               \
                int nb = wn * 32 + ni * 8;                                   \
                bF[ni][0] = __float_as_uint(Bs[cur][kb + tq][nb + g]);       \
                bF[ni][1] = __float_as_uint(Bs[cur][kb + tq + 4][nb + g]);   \
            }                                                                \
            _Pragma("unroll") for (int mi = 0; mi < 4; ++mi)                 \
            _Pragma("unroll") for (int ni = 0; ni < 4; ++ni)                 \
                MMA_TF32(acc[mi][ni], aF[mi], bF[ni]);                       \
        }                                                                    \
    } while (0)

#define GEMM_MAINLOOP(KDIM)                                                  \
    do {                                                                     \
        _Pragma("unroll") for (int i = 0; i < 2; ++i) {                      \
            fa[i] = *(const float4*)(Arow[i]);                               \
            fb[i] = *(const float4*)(Brow[i]);                               \
        }                                                                    \
        STS_STAGE(0);                                                        \
        __syncthreads();                                                     \
        const int KT = (KDIM) / BKT;                                         \
        for (int kt = 0; kt < KT; ++kt) {                                    \
            const int cur = kt & 1;                                          \
            if (kt + 1 < KT) {                                               \
                const int k0 = (kt + 1) * BKT;                               \
                _Pragma("unroll") for (int i = 0; i < 2; ++i) {              \
                    fa[i] = *(const float4*)(Arow[i] + k0);                  \
                    fb[i] = *(const float4*)(Brow[i] + k0);                  \
                }                                                            \
            }                                                                \
            COMPUTE_STAGE(cur);                                              \
            if (kt + 1 < KT) {                                               \
                STS_STAGE(cur ^ 1);                                          \
                __syncthreads();                                             \
            }                                                                \
        }                                                                    \
    } while (0)

// ---------------- GEMM1: H = gelu(X_gathered @ W1[e]^T) --------------------
__global__ __launch_bounds__(NTHREADS, 2)
void k_gemm1(const float* __restrict__ x, const float* __restrict__ W1) {
    __shared__ float As[2][BKT][BM + 4];
    __shared__ float Bs[2][BKT][BN + 4];

    const int e = blockIdx.z;
    const int cnt = g_cnt[e];
    const int m0 = blockIdx.x * BM;
    if (m0 >= cnt) return;
    const int n0 = blockIdx.y * BN;

    GEMM_PROLOG();

    const float* Arow[2];
    const float* Brow[2];
    int ar[2], ac[2];
#pragma unroll
    for (int i = 0; i < 2; ++i) {
        int idx = tid + i * 256;
        int r = idx >> 2, c = (idx & 3) << 2;
        ar[i] = r; ac[i] = c;
        int m = m0 + r;
        int tok = (m < cnt) ? g_list[e * T_TOK + m] : 0;
        Arow[i] = x + (size_t)tok * HDIM + c;
        Brow[i] = W1 + (size_t)e * HFF * HDIM + (size_t)(n0 + r) * HDIM + c;
    }

    float4 fa[2], fb[2];
    GEMM_MAINLOOP(HDIM);

    // Epilogue: gelu + store H rows (guard: never write rows >= cnt — those
    // slots belong to the next expert's region).
    const int base = g_base[e];
#pragma unroll
    for (int mi = 0; mi < 4; ++mi) {
        const int rb = wm * 64 + mi * 16;
        const int mA = m0 + rb + g;
        const int mB = mA + 8;
#pragma unroll
        for (int ni = 0; ni < 4; ++ni) {
            const int col = n0 + wn * 32 + ni * 8 + 2 * tq;
            if (mA < cnt) {
                float2 v;
                v.x = gelu_tanh(acc[mi][ni][0]);
                v.y = gelu_tanh(acc[mi][ni][1]);
                *(float2*)&g_hbuf[(size_t)(base + mA) * HFF + col] = v;
            }
            if (mB < cnt) {
                float2 v;
                v.x = gelu_tanh(acc[mi][ni][2]);
                v.y = gelu_tanh(acc[mi][ni][3]);
                *(float2*)&g_hbuf[(size_t)(base + mB) * HFF + col] = v;
            }
        }
    }
}

// ---------------- GEMM2: out[tok] += gate * (H @ W2[e]^T) -------------------
__global__ __launch_bounds__(NTHREADS, 2)
void k_gemm2(const float* __restrict__ W2, float* __restrict__ out) {
    __shared__ float As[2][BKT][BM + 4];
    __shared__ float Bs[2][BKT][BN + 4];

    const int e = blockIdx.z;
    const int cnt = g_cnt[e];
    const int m0 = blockIdx.x * BM;
    if (m0 >= cnt) return;
    const int n0 = blockIdx.y * BN;
    const int base = g_base[e];

    GEMM_PROLOG();

    const float* Arow[2];
    const float* Brow[2];
    int ar[2], ac[2];
#pragma unroll
    for (int i = 0; i < 2; ++i) {
        int idx = tid + i * 256;
        int r = idx >> 2, c = (idx & 3) << 2;
        ar[i] = r; ac[i] = c;
        // rows >= cnt read garbage inside the padded buffer (results discarded)
        Arow[i] = g_hbuf + (size_t)(base + m0 + r) * HFF + c;
        Brow[i] = W2 + (size_t)e * HDIM * HFF + (size_t)(n0 + r) * HFF + c;
    }

    float4 fa[2], fb[2];
    GEMM_MAINLOOP(HFF);

    // Epilogue: gated accumulate into out (token may appear for 2 experts).
#pragma unroll
    for (int mi = 0; mi < 4; ++mi) {
        const int rb = wm * 64 + mi * 16;
        const int mA = m0 + rb + g;
        const int mB = mA + 8;
        int tokA = 0, tokB = 0;
        float gA = 0.f, gB = 0.f;
        if (mA < cnt) { tokA = g_list[e * T_TOK + mA]; gA = g_gval[e * T_TOK + mA]; }
        if (mB < cnt) { tokB = g_list[e * T_TOK + mB]; gB = g_gval[e * T_TOK + mB]; }
#pragma unroll
        for (int ni = 0; ni < 4; ++ni) {
            const int col = n0 + wn * 32 + ni * 8 + 2 * tq;
            if (mA < cnt) {
                atomicAdd(&out[(size_t)tokA * HDIM + col],     gA * acc[mi][ni][0]);
                atomicAdd(&out[(size_t)tokA * HDIM + col + 1], gA * acc[mi][ni][1]);
            }
            if (mB < cnt) {
                atomicAdd(&out[(size_t)tokB * HDIM + col],     gB * acc[mi][ni][2]);
                atomicAdd(&out[(size_t)tokB * HDIM + col + 1], gB * acc[mi][ni][3]);
            }
        }
    }
}

// ---------------- launch ----------------------------------------------------
extern "C" void kernel_launch(void* const* d_in, const int* in_sizes, int n_in,
                              void* d_out, int out_size) {
    const float* x     = (const float*)d_in[0];
    const float* probs = (const float*)d_in[1];
    const void*  idx   = d_in[2];
    const float* W1    = (const float*)d_in[3];
    const float* W2    = (const float*)d_in[4];
    float* out = (float*)d_out;

    const int n4 = out_size / 4;  // out_size = 4M float elements
    k_zero<<<(n4 + 255) / 256, 256>>>((float4*)out, n4);
    k_detect<<<32, 256>>>((const int*)idx);
    k_gate<<<(T_TOK + 255) / 256, 256>>>(idx, probs);
    k_prefix<<<1, 1>>>();

    dim3 g1(T_TOK / BM, HFF / BN, NEXP);   // (32, 32, 8); tail CTAs self-prune
    k_gemm1<<<g1, NTHREADS>>>(x, W1);

    dim3 g2(T_TOK / BM, HDIM / BN, NEXP);  // (32, 8, 8)
    k_gemm2<<<g2, NTHREADS>>>(W2, out);
}

// round 7
// speedup vs baseline: 1.0002x; 1.0002x over previous
#include <cuda_runtime.h>
#include <cstdint>

// Problem constants
#define T_TOK 4096      // B*S
#define HDIM  1024
#define HFF   4096
#define NEXP  8
#define KTOP  2

// GEMM tiling
#define BM 128
#define BN 128
#define BKT 16
#define NTHREADS 256

// ---------------- device scratch (static: no allocations allowed) ----------
__device__ int   g_cnt[NEXP];
__device__ int   g_base[NEXP];
__device__ int   g_list[NEXP * T_TOK];
__device__ float g_gval[NEXP * T_TOK];
__device__ int   g_i32flag;
// H buffer: one row per (expert, slot) entry; padded by BM rows so tail tiles
// of the LAST expert can be read (never written) without OOB.
__device__ float g_hbuf[(size_t)(T_TOK * KTOP + BM) * HFF];

// ---------------- helpers --------------------------------------------------
__device__ __forceinline__ float tf32r(float x) {
    uint32_t o;
    asm("cvt.rna.tf32.f32 %0, %1;" : "=r"(o) : "f"(x));
    return __uint_as_float(o);
}

__device__ __forceinline__ float gelu_tanh(float x) {
    // jax.nn.gelu default: approximate=True (tanh form)
    float x3 = x * x * x;
    float t = tanhf(0.7978845608028654f * (x + 0.044715f * x3));
    return 0.5f * x * (1.0f + t);
}

#define MMA_TF32(c, a, b)                                                   \
    asm volatile(                                                           \
        "mma.sync.aligned.m16n8k8.row.col.f32.tf32.tf32.f32 "               \
        "{%0,%1,%2,%3}, {%4,%5,%6,%7}, {%8,%9}, {%0,%1,%2,%3};"             \
        : "+f"((c)[0]), "+f"((c)[1]), "+f"((c)[2]), "+f"((c)[3])            \
        : "r"((a)[0]), "r"((a)[1]), "r"((a)[2]), "r"((a)[3]),               \
          "r"((b)[0]), "r"((b)[1]))

// ---------------- small kernels --------------------------------------------
__global__ void k_zero(float4* out4, int n4) {
    int i = blockIdx.x * blockDim.x + threadIdx.x;
    if (i < n4) out4[i] = make_float4(0.f, 0.f, 0.f, 0.f);
    if (i < NEXP) g_cnt[i] = 0;
    if (i == 0) g_i32flag = 0;
}

// topk_indices may be int64 (x64 on) or int32 (default jax). Values are 0..7,
// so with int64 every odd int32 word is 0. Scan only the first T*K int32
// words (in-bounds for BOTH dtypes): any nonzero odd word => int32 data.
__global__ void k_detect(const int* __restrict__ idx32) {
    int i = blockIdx.x * blockDim.x + threadIdx.x;
    int v = 0;
    for (int j = i; j < (T_TOK * KTOP) / 2; j += gridDim.x * blockDim.x)
        v |= idx32[2 * j + 1];
    if (v) atomicOr(&g_i32flag, 1);
}

__global__ void k_gate(const void* __restrict__ idx_raw,
                       const float* __restrict__ probs) {
    int t = blockIdx.x * blockDim.x + threadIdx.x;
    if (t >= T_TOK) return;
    int e0, e1;
    if (g_i32flag) {
        const int* p = (const int*)idx_raw;
        e0 = p[2 * t]; e1 = p[2 * t + 1];
    } else {
        const long long* p = (const long long*)idx_raw;
        e0 = (int)p[2 * t]; e1 = (int)p[2 * t + 1];
    }
    float p0 = probs[2 * t], p1 = probs[2 * t + 1];
    if (e0 == e1) { p0 = fmaxf(p0, p1); e1 = -1; }  // max over k dedups
    if ((unsigned)e0 < NEXP) {
        int pos = atomicAdd(&g_cnt[e0], 1);
        g_list[e0 * T_TOK + pos] = t;
        g_gval[e0 * T_TOK + pos] = p0;
    }
    if ((unsigned)e1 < NEXP) {
        int pos = atomicAdd(&g_cnt[e1], 1);
        g_list[e1 * T_TOK + pos] = t;
        g_gval[e1 * T_TOK + pos] = p1;
    }
}

__global__ void k_prefix() {
    int s = 0;
    for (int e = 0; e < NEXP; ++e) { g_base[e] = s; s += g_cnt[e]; }
}

// ---------------- GEMM mainloop shared pieces (macros for two kernels) -----
// Smem layout: [stage][k][row+pad]  — fragment loads are bank-conflict-free.

#define GEMM_PROLOG()                                                        \
    const int tid = threadIdx.x;                                             \
    const int lane = tid & 31, warp = tid >> 5;                              \
    const int wm = warp & 1, wn = warp >> 1;                                 \
    const int g = lane >> 2, tq = lane & 3;                                  \
    float acc[4][4][4];                                                      \
    _Pragma("unroll") for (int mi = 0; mi < 4; ++mi)                         \
    _Pragma("unroll") for (int ni = 0; ni < 4; ++ni)                         \
    _Pragma("unroll") for (int ci = 0; ci < 4; ++ci) acc[mi][ni][ci] = 0.f;

#define STS_STAGE(s)                                                         \
    do {                                                                     \
        _Pragma("unroll") for (int i = 0; i < 2; ++i) {                      \
            As[s][ac[i] + 0][ar[i]] = tf32r(fa[i].x);                        \
            As[s][ac[i] + 1][ar[i]] = tf32r(fa[i].y);                        \
            As[s][ac[i] + 2][ar[i]] = tf32r(fa[i].z);                        \
            As[s][ac[i] + 3][ar[i]] = tf32r(fa[i].w);                        \
            Bs[s][ac[i] + 0][ar[i]] = tf32r(fb[i].x);                        \
            Bs[s][ac[i] + 1][ar[i]] = tf32r(fb[i].y);                        \
            Bs[s][ac[i] + 2][ar[i]] = tf32r(fb[i].z);                        \
            Bs[s][ac[i] + 3][ar[i]] = tf32r(fb[i].w);                        \
        }                                                                    \
    } while (0)

#define COMPUTE_STAGE(cur)                                                   \
    do {                                                                     \
        _Pragma("unroll") for (int ks = 0; ks < 2; ++ks) {                   \
            const int kb = ks * 8;                                           \
            uint32_t aF[4][4], bF[4][2];                                     \
            _Pragma("unroll") for (int mi = 0; mi < 4; ++mi) {               \
                int rb = wm * 64 + mi * 16;                                  \
                aF[mi][0] = __float_as_uint(As[cur][kb + tq][rb + g]);       \
                aF[mi][1] = __float_as_uint(As[cur][kb + tq][rb + g + 8]);   \
                aF[mi][2] = __float_as_uint(As[cur][kb + tq + 4][rb + g]);   \
                aF[mi][3] = __float_as_uint(As[cur][kb + tq + 4][rb + g + 8]);\
            }                                                                \
            _Pragma("unroll") for (int ni = 0; ni < 4; ++ni) {               \
                int nb = wn * 32 + ni * 8;                                   \
                bF[ni][0] = __float_as_uint(Bs[cur][kb + tq][nb + g]);       \
                bF[ni][1] = __float_as_uint(Bs[cur][kb + tq + 4][nb + g]);   \
            }                                                                \
            _Pragma("unroll") for (int mi = 0; mi < 4; ++mi)                 \
            _Pragma("unroll") for (int ni = 0; ni < 4; ++ni)                 \
                MMA_TF32(acc[mi][ni], aF[mi], bF[ni]);                       \
        }                                                                    \
    } while (0)

#define GEMM_MAINLOOP(KDIM)                                                  \
    do {                                                                     \
        _Pragma("unroll") for (int i = 0; i < 2; ++i) {                      \
            fa[i] = *(const float4*)(Arow[i]);                               \
            fb[i] = *(const float4*)(Brow[i]);                               \
        }                                                                    \
        STS_STAGE(0);                                                        \
        __syncthreads();                                                     \
        const int KT = (KDIM) / BKT;                                         \
        for (int kt = 0; kt < KT; ++kt) {                                    \
            const int cur = kt & 1;                                          \
            if (kt + 1 < KT) {                                               \
                const int k0 = (kt + 1) * BKT;                               \
                _Pragma("unroll") for (int i = 0; i < 2; ++i) {              \
                    fa[i] = *(const float4*)(Arow[i] + k0);                  \
                    fb[i] = *(const float4*)(Brow[i] + k0);                  \
                }                                                            \
            }                                                                \
            COMPUTE_STAGE(cur);                                              \
            if (kt + 1 < KT) {                                               \
                STS_STAGE(cur ^ 1);                                          \
                __syncthreads();                                             \
            }                                                                \
        }                                                                    \
    } while (0)

// ---------------- GEMM1: H = gelu(X_gathered @ W1[e]^T) --------------------
__global__ __launch_bounds__(NTHREADS, 2)
void k_gemm1(const float* __restrict__ x, const float* __restrict__ W1) {
    __shared__ float As[2][BKT][BM + 4];
    __shared__ float Bs[2][BKT][BN + 4];

    const int e = blockIdx.z;
    const int cnt = g_cnt[e];
    const int m0 = blockIdx.x * BM;
    if (m0 >= cnt) return;
    const int n0 = blockIdx.y * BN;

    GEMM_PROLOG();

    const float* Arow[2];
    const float* Brow[2];
    int ar[2], ac[2];
#pragma unroll
    for (int i = 0; i < 2; ++i) {
        int idx = tid + i * 256;
        int r = idx >> 2, c = (idx & 3) << 2;
        ar[i] = r; ac[i] = c;
        int m = m0 + r;
        int tok = (m < cnt) ? g_list[e * T_TOK + m] : 0;
        Arow[i] = x + (size_t)tok * HDIM + c;
        Brow[i] = W1 + (size_t)e * HFF * HDIM + (size_t)(n0 + r) * HDIM + c;
    }

    float4 fa[2], fb[2];
    GEMM_MAINLOOP(HDIM);

    // Epilogue: gelu + store H rows (guard: never write rows >= cnt — those
    // slots belong to the next expert's region).
    const int base = g_base[e];
#pragma unroll
    for (int mi = 0; mi < 4; ++mi) {
        const int rb = wm * 64 + mi * 16;
        const int mA = m0 + rb + g;
        const int mB = mA + 8;
#pragma unroll
        for (int ni = 0; ni < 4; ++ni) {
            const int col = n0 + wn * 32 + ni * 8 + 2 * tq;
            if (mA < cnt) {
                float2 v;
                v.x = gelu_tanh(acc[mi][ni][0]);
                v.y = gelu_tanh(acc[mi][ni][1]);
                *(float2*)&g_hbuf[(size_t)(base + mA) * HFF + col] = v;
            }
            if (mB < cnt) {
                float2 v;
                v.x = gelu_tanh(acc[mi][ni][2]);
                v.y = gelu_tanh(acc[mi][ni][3]);
                *(float2*)&g_hbuf[(size_t)(base + mB) * HFF + col] = v;
            }
        }
    }
}

// ---------------- GEMM2: out[tok] += gate * (H @ W2[e]^T) -------------------
__global__ __launch_bounds__(NTHREADS, 2)
void k_gemm2(const float* __restrict__ W2, float* __restrict__ out) {
    __shared__ float As[2][BKT][BM + 4];
    __shared__ float Bs[2][BKT][BN + 4];

    const int e = blockIdx.z;
    const int cnt = g_cnt[e];
    const int m0 = blockIdx.x * BM;
    if (m0 >= cnt) return;
    const int n0 = blockIdx.y * BN;
    const int base = g_base[e];

    GEMM_PROLOG();

    const float* Arow[2];
    const float* Brow[2];
    int ar[2], ac[2];
#pragma unroll
    for (int i = 0; i < 2; ++i) {
        int idx = tid + i * 256;
        int r = idx >> 2, c = (idx & 3) << 2;
        ar[i] = r; ac[i] = c;
        // rows >= cnt read garbage inside the padded buffer (results discarded)
        Arow[i] = g_hbuf + (size_t)(base + m0 + r) * HFF + c;
        Brow[i] = W2 + (size_t)e * HDIM * HFF + (size_t)(n0 + r) * HFF + c;
    }

    float4 fa[2], fb[2];
    GEMM_MAINLOOP(HFF);

    // Epilogue: gated accumulate into out (token may appear for 2 experts).
#pragma unroll
    for (int mi = 0; mi < 4; ++mi) {
        const int rb = wm * 64 + mi * 16;
        const int mA = m0 + rb + g;
        const int mB = mA + 8;
        int tokA = 0, tokB = 0;
        float gA = 0.f, gB = 0.f;
        if (mA < cnt) { tokA = g_list[e * T_TOK + mA]; gA = g_gval[e * T_TOK + mA]; }
        if (mB < cnt) { tokB = g_list[e * T_TOK + mB]; gB = g_gval[e * T_TOK + mB]; }
#pragma unroll
        for (int ni = 0; ni < 4; ++ni) {
            const int col = n0 + wn * 32 + ni * 8 + 2 * tq;
            if (mA < cnt) {
                atomicAdd(&out[(size_t)tokA * HDIM + col],     gA * acc[mi][ni][0]);
                atomicAdd(&out[(size_t)tokA * HDIM + col + 1], gA * acc[mi][ni][1]);
            }
            if (mB < cnt) {
                atomicAdd(&out[(size_t)tokB * HDIM + col],     gB * acc[mi][ni][2]);
                atomicAdd(&out[(size_t)tokB * HDIM + col + 1], gB * acc[mi][ni][3]);
            }
        }
    }
}

// ---------------- launch ----------------------------------------------------
extern "C" void kernel_launch(void* const* d_in, const int* in_sizes, int n_in,
                              void* d_out, int out_size) {
    const float* x     = (const float*)d_in[0];
    const float* probs = (const float*)d_in[1];
    const void*  idx   = d_in[2];
    const float* W1    = (const float*)d_in[3];
    const float* W2    = (const float*)d_in[4];
    float* out = (float*)d_out;

    const int n4 = out_size / 4;  // out_size = 4M float elements
    k_zero<<<(n4 + 255) / 256, 256>>>((float4*)out, n4);
    k_detect<<<32, 256>>>((const int*)idx);
    k_gate<<<(T_TOK + 255) / 256, 256>>>(idx, probs);
    k_prefix<<<1, 1>>>();

    dim3 g1(T_TOK / BM, HFF / BN, NEXP);   // (32, 32, 8); tail CTAs self-prune
    k_gemm1<<<g1, NTHREADS>>>(x, W1);

    dim3 g2(T_TOK / BM, HDIM / BN, NEXP);  // (32, 8, 8)
    k_gemm2<<<g2, NTHREADS>>>(W2, out);
}

// round 8
// speedup vs baseline: 1.0002x; 1.0001x over previous
#include <cuda_runtime.h>
#include <cstdint>

// Problem constants
#define T_TOK 4096      // B*S
#define HDIM  1024
#define HFF   4096
#define NEXP  8
#define KTOP  2

// GEMM tiling
#define BM 128
#define BN 128
#define BKT 16
#define NTHREADS 256

// ---------------- device scratch (static: no allocations allowed) ----------
__device__ int   g_cnt[NEXP];
__device__ int   g_base[NEXP];
__device__ int   g_list[NEXP * T_TOK];
__device__ float g_gval[NEXP * T_TOK];
__device__ int   g_i32flag;
// H buffer: one row per (expert, slot) entry; padded by BM rows so tail tiles
// of the LAST expert can be read (never written) without OOB.
__device__ float g_hbuf[(size_t)(T_TOK * KTOP + BM) * HFF];

// ---------------- helpers --------------------------------------------------
__device__ __forceinline__ float tf32r(float x) {
    uint32_t o;
    asm("cvt.rna.tf32.f32 %0, %1;" : "=r"(o) : "f"(x));
    return __uint_as_float(o);
}

__device__ __forceinline__ float gelu_tanh(float x) {
    // jax.nn.gelu default: approximate=True (tanh form)
    float x3 = x * x * x;
    float t = tanhf(0.7978845608028654f * (x + 0.044715f * x3));
    return 0.5f * x * (1.0f + t);
}

#define MMA_TF32(c, a, b)                                                   \
    asm volatile(                                                           \
        "mma.sync.aligned.m16n8k8.row.col.f32.tf32.tf32.f32 "               \
        "{%0,%1,%2,%3}, {%4,%5,%6,%7}, {%8,%9}, {%0,%1,%2,%3};"             \
        : "+f"((c)[0]), "+f"((c)[1]), "+f"((c)[2]), "+f"((c)[3])            \
        : "r"((a)[0]), "r"((a)[1]), "r"((a)[2]), "r"((a)[3]),               \
          "r"((b)[0]), "r"((b)[1]))

// ---------------- small kernels --------------------------------------------
__global__ void k_zero(float4* out4, int n4) {
    int i = blockIdx.x * blockDim.x + threadIdx.x;
    if (i < n4) out4[i] = make_float4(0.f, 0.f, 0.f, 0.f);
    if (i < NEXP) g_cnt[i] = 0;
    if (i == 0) g_i32flag = 0;
}

// topk_indices may be int64 (x64 on) or int32 (default jax). Values are 0..7,
// so with int64 every odd int32 word is 0. Scan only the first T*K int32
// words (in-bounds for BOTH dtypes): any nonzero odd word => int32 data.
__global__ void k_detect(const int* __restrict__ idx32) {
    int i = blockIdx.x * blockDim.x + threadIdx.x;
    int v = 0;
    for (int j = i; j < (T_TOK * KTOP) / 2; j += gridDim.x * blockDim.x)
        v |= idx32[2 * j + 1];
    if (v) atomicOr(&g_i32flag, 1);
}

__global__ void k_gate(const void* __restrict__ idx_raw,
                       const float* __restrict__ probs) {
    int t = blockIdx.x * blockDim.x + threadIdx.x;
    if (t >= T_TOK) return;
    int e0, e1;
    if (g_i32flag) {
        const int* p = (const int*)idx_raw;
        e0 = p[2 * t]; e1 = p[2 * t + 1];
    } else {
        const long long* p = (const long long*)idx_raw;
        e0 = (int)p[2 * t]; e1 = (int)p[2 * t + 1];
    }
    float p0 = probs[2 * t], p1 = probs[2 * t + 1];
    if (e0 == e1) { p0 = fmaxf(p0, p1); e1 = -1; }  // max over k dedups
    if ((unsigned)e0 < NEXP) {
        int pos = atomicAdd(&g_cnt[e0], 1);
        g_list[e0 * T_TOK + pos] = t;
        g_gval[e0 * T_TOK + pos] = p0;
    }
    if ((unsigned)e1 < NEXP) {
        int pos = atomicAdd(&g_cnt[e1], 1);
        g_list[e1 * T_TOK + pos] = t;
        g_gval[e1 * T_TOK + pos] = p1;
    }
}

__global__ void k_prefix() {
    int s = 0;
    for (int e = 0; e < NEXP; ++e) { g_base[e] = s; s += g_cnt[e]; }
}

// ---------------- GEMM mainloop shared pieces (macros for two kernels) -----
// Smem layout: [stage][k][row+pad]  — fragment loads are bank-conflict-free.

#define GEMM_PROLOG()                                                        \
    const int tid = threadIdx.x;                                             \
    const int lane = tid & 31, warp = tid >> 5;                              \
    const int wm = warp & 1, wn = warp >> 1;                                 \
    const int g = lane >> 2, tq = lane & 3;                                  \
    float acc[4][4][4];                                                      \
    _Pragma("unroll") for (int mi = 0; mi < 4; ++mi)                         \
    _Pragma("unroll") for (int ni = 0; ni < 4; ++ni)                         \
    _Pragma("unroll") for (int ci = 0; ci < 4; ++ci) acc[mi][ni][ci] = 0.f;

#define STS_STAGE(s)                                                         \
    do {                                                                     \
        _Pragma("unroll") for (int i = 0; i < 2; ++i) {                      \
            As[s][ac[i] + 0][ar[i]] = tf32r(fa[i].x);                        \
            As[s][ac[i] + 1][ar[i]] = tf32r(fa[i].y);                        \
            As[s][ac[i] + 2][ar[i]] = tf32r(fa[i].z);                        \
            As[s][ac[i] + 3][ar[i]] = tf32r(fa[i].w);                        \
            Bs[s][ac[i] + 0][ar[i]] = tf32r(fb[i].x);                        \
            Bs[s][ac[i] + 1][ar[i]] = tf32r(fb[i].y);                        \
            Bs[s][ac[i] + 2][ar[i]] = tf32r(fb[i].z);                        \
            Bs[s][ac[i] + 3][ar[i]] = tf32r(fb[i].w);                        \
        }                                                                    \
    } while (0)

#define COMPUTE_STAGE(cur)                                                   \
    do {                                                                     \
        _Pragma("unroll") for (int ks = 0; ks < 2; ++ks) {                   \
            const int kb = ks * 8;                                           \
            uint32_t aF[4][4], bF[4][2];                                     \
            _Pragma("unroll") for (int mi = 0; mi < 4; ++mi) {               \
                int rb = wm * 64 + mi * 16;                                  \
                aF[mi][0] = __float_as_uint(As[cur][kb + tq][rb + g]);       \
                aF[mi][1] = __float_as_uint(As[cur][kb + tq][rb + g + 8]);   \
                aF[mi][2] = __float_as_uint(As[cur][kb + tq + 4][rb + g]);   \
                aF[mi][3] = __float_as_uint(As[cur][kb + tq + 4][rb + g + 8]);\
            }                                                                \
            _Pragma("unroll") for (int ni = 0; ni < 4; ++ni) {               \
                int nb = wn * 32 + ni * 8;                                   \
                bF[ni][0] = __float_as_uint(Bs[cur][kb + tq][nb + g]);       \
                bF[ni][1] = __float_as_uint(Bs[cur][kb + tq + 4][nb + g]);   \
            }                                                                \
            _Pragma("unroll") for (int mi = 0; mi < 4; ++mi)                 \
            _Pragma("unroll") for (int ni = 0; ni < 4; ++ni)                 \
                MMA_TF32(acc[mi][ni], aF[mi], bF[ni]);                       \
        }                                                                    \
    } while (0)

#define GEMM_MAINLOOP(KDIM)                                                  \
    do {                                                                     \
        _Pragma("unroll") for (int i = 0; i < 2; ++i) {                      \
            fa[i] = *(const float4*)(Arow[i]);                               \
            fb[i] = *(const float4*)(Brow[i]);                               \
        }                                                                    \
        STS_STAGE(0);                                                        \
        __syncthreads();                                                     \
        const int KT = (KDIM) / BKT;                                         \
        for (int kt = 0; kt < KT; ++kt) {                                    \
            const int cur = kt & 1;                                          \
            if (kt + 1 < KT) {                                               \
                const int k0 = (kt + 1) * BKT;                               \
                _Pragma("unroll") for (int i = 0; i < 2; ++i) {              \
                    fa[i] = *(const float4*)(Arow[i] + k0);                  \
                    fb[i] = *(const float4*)(Brow[i] + k0);                  \
                }                                                            \
            }                                                                \
            COMPUTE_STAGE(cur);                                              \
            if (kt + 1 < KT) {                                               \
                STS_STAGE(cur ^ 1);                                          \
                __syncthreads();                                             \
            }                                                                \
        }                                                                    \
    } while (0)

// ---------------- GEMM1: H = gelu(X_gathered @ W1[e]^T) --------------------
__global__ __launch_bounds__(NTHREADS, 2)
void k_gemm1(const float* __restrict__ x, const float* __restrict__ W1) {
    __shared__ float As[2][BKT][BM + 4];
    __shared__ float Bs[2][BKT][BN + 4];

    const int e = blockIdx.z;
    const int cnt = g_cnt[e];
    const int m0 = blockIdx.x * BM;
    if (m0 >= cnt) return;
    const int n0 = blockIdx.y * BN;

    GEMM_PROLOG();

    const float* Arow[2];
    const float* Brow[2];
    int ar[2], ac[2];
#pragma unroll
    for (int i = 0; i < 2; ++i) {
        int idx = tid + i * 256;
        int r = idx >> 2, c = (idx & 3) << 2;
        ar[i] = r; ac[i] = c;
        int m = m0 + r;
        int tok = (m < cnt) ? g_list[e * T_TOK + m] : 0;
        Arow[i] = x + (size_t)tok * HDIM + c;
        Brow[i] = W1 + (size_t)e * HFF * HDIM + (size_t)(n0 + r) * HDIM + c;
    }

    float4 fa[2], fb[2];
    GEMM_MAINLOOP(HDIM);

    // Epilogue: gelu + store H rows (guard: never write rows >= cnt — those
    // slots belong to the next expert's region).
    const int base = g_base[e];
#pragma unroll
    for (int mi = 0; mi < 4; ++mi) {
        const int rb = wm * 64 + mi * 16;
        const int mA = m0 + rb + g;
        const int mB = mA + 8;
#pragma unroll
        for (int ni = 0; ni < 4; ++ni) {
            const int col = n0 + wn * 32 + ni * 8 + 2 * tq;
            if (mA < cnt) {
                float2 v;
                v.x = gelu_tanh(acc[mi][ni][0]);
                v.y = gelu_tanh(acc[mi][ni][1]);
                *(float2*)&g_hbuf[(size_t)(base + mA) * HFF + col] = v;
            }
            if (mB < cnt) {
                float2 v;
                v.x = gelu_tanh(acc[mi][ni][2]);
                v.y = gelu_tanh(acc[mi][ni][3]);
                *(float2*)&g_hbuf[(size_t)(base + mB) * HFF + col] = v;
            }
        }
    }
}

// ---------------- GEMM2: out[tok] += gate * (H @ W2[e]^T) -------------------
__global__ __launch_bounds__(NTHREADS, 2)
void k_gemm2(const float* __restrict__ W2, float* __restrict__ out) {
    __shared__ float As[2][BKT][BM + 4];
    __shared__ float Bs[2][BKT][BN + 4];

    const int e = blockIdx.z;
    const int cnt = g_cnt[e];
    const int m0 = blockIdx.x * BM;
    if (m0 >= cnt) return;
    const int n0 = blockIdx.y * BN;
    const int base = g_base[e];

    GEMM_PROLOG();

    const float* Arow[2];
    const float* Brow[2];
    int ar[2], ac[2];
#pragma unroll
    for (int i = 0; i < 2; ++i) {
        int idx = tid + i * 256;
        int r = idx >> 2, c = (idx & 3) << 2;
        ar[i] = r; ac[i] = c;
        // rows >= cnt read garbage inside the padded buffer (results discarded)
        Arow[i] = g_hbuf + (size_t)(base + m0 + r) * HFF + c;
        Brow[i] = W2 + (size_t)e * HDIM * HFF + (size_t)(n0 + r) * HFF + c;
    }

    float4 fa[2], fb[2];
    GEMM_MAINLOOP(HFF);

    // Epilogue: gated accumulate into out (token may appear for 2 experts).
#pragma unroll
    for (int mi = 0; mi < 4; ++mi) {
        const int rb = wm * 64 + mi * 16;
        const int mA = m0 + rb + g;
        const int mB = mA + 8;
        int tokA = 0, tokB = 0;
        float gA = 0.f, gB = 0.f;
        if (mA < cnt) { tokA = g_list[e * T_TOK + mA]; gA = g_gval[e * T_TOK + mA]; }
        if (mB < cnt) { tokB = g_list[e * T_TOK + mB]; gB = g_gval[e * T_TOK + mB]; }
#pragma unroll
        for (int ni = 0; ni < 4; ++ni) {
            const int col = n0 + wn * 32 + ni * 8 + 2 * tq;
            if (mA < cnt) {
                atomicAdd(&out[(size_t)tokA * HDIM + col],     gA * acc[mi][ni][0]);
                atomicAdd(&out[(size_t)tokA * HDIM + col + 1], gA * acc[mi][ni][1]);
            }
            if (mB < cnt) {
                atomicAdd(&out[(size_t)tokB * HDIM + col],     gB * acc[mi][ni][2]);
                atomicAdd(&out[(size_t)tokB * HDIM + col + 1], gB * acc[mi][ni][3]);
            }
        }
    }
}

// ---------------- launch ----------------------------------------------------
extern "C" void kernel_launch(void* const* d_in, const int* in_sizes, int n_in,
                              void* d_out, int out_size) {
    const float* x     = (const float*)d_in[0];
    const float* probs = (const float*)d_in[1];
    const void*  idx   = d_in[2];
    const float* W1    = (const float*)d_in[3];
    const float* W2    = (const float*)d_in[4];
    float* out = (float*)d_out;

    const int n4 = out_size / 4;  // out_size = 4M float elements
    k_zero<<<(n4 + 255) / 256, 256>>>((float4*)out, n4);
    k_detect<<<32, 256>>>((const int*)idx);
    k_gate<<<(T_TOK + 255) / 256, 256>>>(idx, probs);
    k_prefix<<<1, 1>>>();

    dim3 g1(T_TOK / BM, HFF / BN, NEXP);   // (32, 32, 8); tail CTAs self-prune
    k_gemm1<<<g1, NTHREADS>>>(x, W1);

    dim3 g2(T_TOK / BM, HDIM / BN, NEXP);  // (32, 8, 8)
    k_gemm2<<<g2, NTHREADS>>>(W2, out);
}

// round 10
// speedup vs baseline: 1.3033x; 1.3030x over previous
#include <cuda_runtime.h>
#include <cstdint>

// ---------------- problem constants ----------------
#define T_TOK 4096      // B*S
#define HDIM  1024
#define HFF   4096
#define NEXP  8
#define WELEM (NEXP * HFF * HDIM)     // 33554432 floats per weight tensor

// ---------------- GEMM tiling ----------------
#define BM 128
#define BN 128
#define KC 16                          // K per pipeline chunk
#define NSTAGE 3
#define ROWW 20                        // padded smem row stride in floats (80B = 5 x 16B)
#define ABYTES (BM * ROWW * 4)         // 10240 B per operand per stage
#define STAGE_BYTES (2 * ABYTES)       // 20480 B
#define DYN_SMEM (NSTAGE * STAGE_BYTES) // 61440 B -> 2 CTAs/SM
#define NTHR 256

// ---------------- device scratch (no allocations allowed) ----------------
__device__ int   g_cnt[NEXP];
__device__ int   g_base[NEXP];
__device__ int   g_list[NEXP * T_TOK];
__device__ float g_gval[NEXP * T_TOK];
__device__ int   g_i32flag;
__device__ __align__(16) float g_xr[T_TOK * HDIM];        // tf32-rounded x
__device__ __align__(16) float g_w1r[WELEM];              // tf32-rounded W1
__device__ __align__(16) float g_w2r[WELEM];              // tf32-rounded W2
// H rows (already tf32-rounded); padded by BM rows so tail tiles of the last
// expert can be READ (never written) without OOB.
__device__ __align__(16) float g_hbuf[(size_t)(T_TOK * 2 + BM) * HFF];

// ---------------- helpers ----------------
__device__ __forceinline__ uint32_t smem_u32(const void* p) {
    uint32_t a;
    asm("{ .reg .u64 t; cvta.to.shared.u64 t, %1; cvt.u32.u64 %0, t; }" : "=r"(a) : "l"(p));
    return a;
}
__device__ __forceinline__ float tf32r(float x) {
    uint32_t o;
    asm("cvt.rna.tf32.f32 %0, %1;" : "=r"(o) : "f"(x));
    return __uint_as_float(o);
}
__device__ __forceinline__ float gelu_t(float x) {
    float t = tanhf(0.7978845608028654f * (x + 0.044715f * x * x * x));
    return 0.5f * x * (1.0f + t);
}

#define MMA_TF32(c, a, b)                                                   \
    asm volatile(                                                           \
        "mma.sync.aligned.m16n8k8.row.col.f32.tf32.tf32.f32 "               \
        "{%0,%1,%2,%3}, {%4,%5,%6,%7}, {%8,%9}, {%0,%1,%2,%3};"             \
        : "+f"((c)[0]), "+f"((c)[1]), "+f"((c)[2]), "+f"((c)[3])            \
        : "r"((a)[0]), "r"((a)[1]), "r"((a)[2]), "r"((a)[3]),               \
          "r"((b)[0]), "r"((b)[1]))

#define CP_ASYNC16(dst, src)                                                \
    asm volatile("cp.async.cg.shared.global [%0], [%1], 16;"                \
                 :: "r"(dst), "l"(src) : "memory")
#define CP_COMMIT()  asm volatile("cp.async.commit_group;" ::: "memory")

// ---------------- small kernels (validated in rounds 3-8) ----------------
__global__ void k_zero(float4* out4, int n4) {
    int i = blockIdx.x * blockDim.x + threadIdx.x;
    if (i < n4) out4[i] = make_float4(0.f, 0.f, 0.f, 0.f);
    if (i < NEXP) g_cnt[i] = 0;
    if (i == 0) g_i32flag = 0;
}

__global__ void k_detect(const int* __restrict__ idx32) {
    int i = blockIdx.x * blockDim.x + threadIdx.x;
    int v = 0;
    for (int j = i; j < (T_TOK * 2) / 2; j += gridDim.x * blockDim.x)
        v |= idx32[2 * j + 1];
    if (v) atomicOr(&g_i32flag, 1);
}

__global__ void k_gate(const void* __restrict__ idx_raw, const float* __restrict__ probs) {
    int t = blockIdx.x * blockDim.x + threadIdx.x;
    if (t >= T_TOK) return;
    int e0, e1;
    if (g_i32flag) {
        const int* p = (const int*)idx_raw;
        e0 = p[2 * t]; e1 = p[2 * t + 1];
    } else {
        const long long* p = (const long long*)idx_raw;
        e0 = (int)p[2 * t]; e1 = (int)p[2 * t + 1];
    }
    float p0 = probs[2 * t], p1 = probs[2 * t + 1];
    if (e0 == e1) { p0 = fmaxf(p0, p1); e1 = -1; }   // max over k dedups
    if ((unsigned)e0 < NEXP) {
        int pos = atomicAdd(&g_cnt[e0], 1);
        g_list[e0 * T_TOK + pos] = t;
        g_gval[e0 * T_TOK + pos] = p0;
    }
    if ((unsigned)e1 < NEXP) {
        int pos = atomicAdd(&g_cnt[e1], 1);
        g_list[e1 * T_TOK + pos] = t;
        g_gval[e1 * T_TOK + pos] = p1;
    }
}

__global__ void k_prefix() {
    int s = 0;
    for (int e = 0; e < NEXP; ++e) { g_base[e] = s; s += g_cnt[e]; }
}

// ---------------- prep: tf32-round W1, W2, x into scratch -------------------
__device__ __forceinline__ float4 rnd4(float4 v) {
    v.x = tf32r(v.x); v.y = tf32r(v.y); v.z = tf32r(v.z); v.w = tf32r(v.w);
    return v;
}
__global__ void k_prep(const float4* __restrict__ w1, const float4* __restrict__ w2,
                       const float4* __restrict__ x) {
    const int stride = gridDim.x * blockDim.x;
    float4* o1 = (float4*)g_w1r;
    float4* o2 = (float4*)g_w2r;
    float4* ox = (float4*)g_xr;
    int i0 = blockIdx.x * blockDim.x + threadIdx.x;
    for (int j = i0; j < WELEM / 4; j += stride) {
        o1[j] = rnd4(w1[j]);
        o2[j] = rnd4(w2[j]);
    }
    for (int j = i0; j < (T_TOK * HDIM) / 4; j += stride)
        ox[j] = rnd4(x[j]);
}

// ---------------- grouped GEMM with cp.async 3-stage pipeline ---------------
// G1: H[base+m, n] = tf32( gelu( xr[list[m]] . W1r[e][n] ) ),  KDIM = HDIM
// G2: out[list[m]] += gate[m] * ( H[base+m] . W2r[e][n] ),      KDIM = HFF
extern __shared__ char dynsm[];

template <int KDIM, bool IS_G1>
__global__ __launch_bounds__(NTHR, 2)
void k_gemm(float* __restrict__ outp) {
    const int e = blockIdx.z;
    const int cnt = g_cnt[e];
    const int m0 = blockIdx.x * BM;
    if (m0 >= cnt) return;
    const int n0 = blockIdx.y * BN;
    const int base = g_base[e];

    const int tid = threadIdx.x;
    const int lane = tid & 31, warp = tid >> 5;
    const int wm = warp & 1, wn = warp >> 1;
    const int g = lane >> 2, tq = lane & 3;
    const uint32_t sb = smem_u32(dynsm);

    const float* Bw = IS_G1 ? g_w1r : g_w2r;

    // ---- cp.async mapping: 1024 granules/stage (A 512 + B 512), 4/thread ----
    const float* srcp[4];
    uint32_t dsto[4];
#pragma unroll
    for (int i = 0; i < 4; ++i) {
        int id = tid + i * NTHR;          // 0..1023
        int isB = id >> 9;                // 0: A rows, 1: B rows
        int r = (id >> 2) & 127;
        int gc = id & 3;
        dsto[i] = (uint32_t)(isB * ABYTES + r * (ROWW * 4) + gc * 16);
        if (isB) {
            srcp[i] = Bw + (size_t)e * HFF * HDIM + (size_t)(n0 + r) * KDIM + gc * 4;
        } else if (IS_G1) {
            int m = m0 + r;
            int tok = (m < cnt) ? g_list[e * T_TOK + m] : g_list[e * T_TOK];
            srcp[i] = g_xr + (size_t)tok * KDIM + gc * 4;
        } else {
            srcp[i] = g_hbuf + (size_t)(base + m0 + r) * KDIM + gc * 4;  // padded
        }
    }

    float acc[4][4][4];
#pragma unroll
    for (int mi = 0; mi < 4; ++mi)
#pragma unroll
        for (int ni = 0; ni < 4; ++ni)
#pragma unroll
            for (int ci = 0; ci < 4; ++ci) acc[mi][ni][ci] = 0.f;

    auto issue = [&](int kt, int buf) {
        uint32_t b = sb + buf * STAGE_BYTES;
#pragma unroll
        for (int i = 0; i < 4; ++i)
            CP_ASYNC16(b + dsto[i], srcp[i] + kt * KC);
        CP_COMMIT();
    };

    constexpr int KT = KDIM / KC;
    issue(0, 0);
    issue(1, 1);

    for (int kt = 0; kt < KT; ++kt) {
        if (kt == KT - 1) asm volatile("cp.async.wait_group 0;" ::: "memory");
        else              asm volatile("cp.async.wait_group 1;" ::: "memory");
        __syncthreads();   // stage kt landed for ALL threads; buffer (kt-1)%3 free
        if (kt + 2 < KT) issue(kt + 2, (kt + 2) % 3);

        const float* As = (const float*)(dynsm + (kt % 3) * STAGE_BYTES);
        const float* Bs = As + BM * ROWW;
#pragma unroll
        for (int ks = 0; ks < 2; ++ks) {
            const int kb = ks * 8;
            uint32_t aF[4][4], bF[4][2];
#pragma unroll
            for (int mi = 0; mi < 4; ++mi) {
                const float* ap = As + (wm * 64 + mi * 16 + g) * ROWW + kb + tq;
                aF[mi][0] = __float_as_uint(ap[0]);
                aF[mi][1] = __float_as_uint(ap[8 * ROWW]);
                aF[mi][2] = __float_as_uint(ap[4]);
                aF[mi][3] = __float_as_uint(ap[8 * ROWW + 4]);
            }
#pragma unroll
            for (int ni = 0; ni < 4; ++ni) {
                const float* bp = Bs + (wn * 32 + ni * 8 + g) * ROWW + kb + tq;
                bF[ni][0] = __float_as_uint(bp[0]);
                bF[ni][1] = __float_as_uint(bp[4]);
            }
#pragma unroll
            for (int mi = 0; mi < 4; ++mi)
#pragma unroll
                for (int ni = 0; ni < 4; ++ni)
                    MMA_TF32(acc[mi][ni], aF[mi], bF[ni]);
        }
        // no bottom barrier: next overwrite of buffer kt%3 happens only after
        // the top barrier of iteration kt+1, which all warps reach post-compute.
    }

    // ---- epilogue ----
#pragma unroll
    for (int mi = 0; mi < 4; ++mi) {
        const int mA = m0 + wm * 64 + mi * 16 + g;
        const int mB = mA + 8;
        if (IS_G1) {
            float* rowA = g_hbuf + (size_t)(base + mA) * HFF;
            float* rowB = g_hbuf + (size_t)(base + mB) * HFF;
#pragma unroll
            for (int ni = 0; ni < 4; ++ni) {
                const int col = n0 + wn * 32 + ni * 8 + 2 * tq;
                if (mA < cnt) {
                    float2 v;
                    v.x = tf32r(gelu_t(acc[mi][ni][0]));
                    v.y = tf32r(gelu_t(acc[mi][ni][1]));
                    *(float2*)(rowA + col) = v;
                }
                if (mB < cnt) {
                    float2 v;
                    v.x = tf32r(gelu_t(acc[mi][ni][2]));
                    v.y = tf32r(gelu_t(acc[mi][ni][3]));
                    *(float2*)(rowB + col) = v;
                }
            }
        } else {
            int tokA = 0, tokB = 0;
            float gA = 0.f, gB = 0.f;
            if (mA < cnt) { tokA = g_list[e * T_TOK + mA]; gA = g_gval[e * T_TOK + mA]; }
            if (mB < cnt) { tokB = g_list[e * T_TOK + mB]; gB = g_gval[e * T_TOK + mB]; }
#pragma unroll
            for (int ni = 0; ni < 4; ++ni) {
                const int col = n0 + wn * 32 + ni * 8 + 2 * tq;
                if (mA < cnt) {
                    atomicAdd(&outp[(size_t)tokA * HDIM + col],     gA * acc[mi][ni][0]);
                    atomicAdd(&outp[(size_t)tokA * HDIM + col + 1], gA * acc[mi][ni][1]);
                }
                if (mB < cnt) {
                    atomicAdd(&outp[(size_t)tokB * HDIM + col],     gB * acc[mi][ni][2]);
                    atomicAdd(&outp[(size_t)tokB * HDIM + col + 1], gB * acc[mi][ni][3]);
                }
            }
        }
    }
}

// ---------------- launch ----------------
extern "C" void kernel_launch(void* const* d_in, const int* in_sizes, int n_in,
                              void* d_out, int out_size) {
    const float* x     = (const float*)d_in[0];
    const float* probs = (const float*)d_in[1];
    const void*  idx   = d_in[2];
    const float* W1    = (const float*)d_in[3];
    const float* W2    = (const float*)d_in[4];
    float* out = (float*)d_out;

    cudaFuncSetAttribute(k_gemm<HDIM, true>,
                         cudaFuncAttributeMaxDynamicSharedMemorySize, DYN_SMEM);
    cudaFuncSetAttribute(k_gemm<HFF, false>,
                         cudaFuncAttributeMaxDynamicSharedMemorySize, DYN_SMEM);

    const int n4 = out_size / 4;
    k_zero<<<(n4 + 255) / 256, 256>>>((float4*)out, n4);
    k_detect<<<32, 256>>>((const int*)idx);
    k_gate<<<(T_TOK + 255) / 256, 256>>>(idx, probs);
    k_prefix<<<1, 1>>>();
    k_prep<<<1024, 256>>>((const float4*)W1, (const float4*)W2, (const float4*)x);

    dim3 g1(T_TOK / BM, HFF / BN, NEXP);   // (32, 32, 8); tail CTAs self-prune
    k_gemm<HDIM, true><<<g1, NTHR, DYN_SMEM>>>(nullptr);

    dim3 g2(T_TOK / BM, HDIM / BN, NEXP);  // (32, 8, 8)
    k_gemm<HFF, false><<<g2, NTHR, DYN_SMEM>>>(out);
}

// round 11
// speedup vs baseline: 1.4543x; 1.1159x over previous
#include <cuda_runtime.h>
#include <cstdint>

// ---------------- problem constants ----------------
#define T_TOK 4096      // B*S
#define HDIM  1024
#define HFF   4096
#define NEXP  8
#define WELEM (NEXP * HFF * HDIM)     // 33554432 floats per weight tensor

// ---------------- GEMM tiling ----------------
#define BM 128
#define BN 128
#define KC 16                          // K per pipeline chunk
#define NSTAGE 4
#define ROWW 20                        // padded smem row stride in floats (80B = 5 x 16B)
#define ABYTES (BM * ROWW * 4)         // 10240 B per operand per stage
#define STAGE_BYTES (2 * ABYTES)       // 20480 B
#define DYN_SMEM (NSTAGE * STAGE_BYTES) // 81920 B -> 2 CTAs/SM
#define NTHR 256

// ---------------- device scratch (no allocations allowed) ----------------
__device__ int   g_cnt[NEXP];
__device__ int   g_base[NEXP];
__device__ int   g_list[NEXP * T_TOK];
__device__ float g_gval[NEXP * T_TOK];
__device__ int   g_i32flag;
__device__ __align__(16) float g_xr[T_TOK * HDIM];        // tf32-rounded x
__device__ __align__(16) float g_w1r[WELEM];              // tf32-rounded W1
__device__ __align__(16) float g_w2r[WELEM];              // tf32-rounded W2
// H rows (already tf32-rounded); padded by BM rows so tail tiles of the last
// expert can be READ (never written) without OOB.
__device__ __align__(16) float g_hbuf[(size_t)(T_TOK * 2 + BM) * HFF];

// ---------------- helpers ----------------
__device__ __forceinline__ uint32_t smem_u32(const void* p) {
    uint32_t a;
    asm("{ .reg .u64 t; cvta.to.shared.u64 t, %1; cvt.u32.u64 %0, t; }" : "=r"(a) : "l"(p));
    return a;
}
__device__ __forceinline__ float tf32r(float x) {
    uint32_t o;
    asm("cvt.rna.tf32.f32 %0, %1;" : "=r"(o) : "f"(x));
    return __uint_as_float(o);
}
__device__ __forceinline__ float gelu_t(float x) {
    float t = tanhf(0.7978845608028654f * (x + 0.044715f * x * x * x));
    return 0.5f * x * (1.0f + t);
}

#define MMA_TF32(c, a, b)                                                   \
    asm volatile(                                                           \
        "mma.sync.aligned.m16n8k8.row.col.f32.tf32.tf32.f32 "               \
        "{%0,%1,%2,%3}, {%4,%5,%6,%7}, {%8,%9}, {%0,%1,%2,%3};"             \
        : "+f"((c)[0]), "+f"((c)[1]), "+f"((c)[2]), "+f"((c)[3])            \
        : "r"((a)[0]), "r"((a)[1]), "r"((a)[2]), "r"((a)[3]),               \
          "r"((b)[0]), "r"((b)[1]))

#define CP_ASYNC16(dst, src)                                                \
    asm volatile("cp.async.cg.shared.global [%0], [%1], 16;"                \
                 :: "r"(dst), "l"(src) : "memory")
#define CP_COMMIT()  asm volatile("cp.async.commit_group;" ::: "memory")

// ldmatrix x4: reg k = 8x8-b16 tile k, thread holds 32-bit element
// (row = lane>>2, col = lane&3) of its tile — exactly the tf32 mma fragment.
#define LDSM_X4(r0, r1, r2, r3, addr)                                       \
    asm volatile("ldmatrix.sync.aligned.m8n8.x4.shared.b16 {%0,%1,%2,%3}, [%4];" \
        : "=r"(r0), "=r"(r1), "=r"(r2), "=r"(r3) : "r"(addr))

// ---------------- small kernels (validated rounds 3-10) ----------------
__global__ void k_zero(float4* out4, int n4) {
    int i = blockIdx.x * blockDim.x + threadIdx.x;
    if (i < n4) out4[i] = make_float4(0.f, 0.f, 0.f, 0.f);
    if (i < NEXP) g_cnt[i] = 0;
    if (i == 0) g_i32flag = 0;
}

__global__ void k_detect(const int* __restrict__ idx32) {
    int i = blockIdx.x * blockDim.x + threadIdx.x;
    int v = 0;
    for (int j = i; j < (T_TOK * 2) / 2; j += gridDim.x * blockDim.x)
        v |= idx32[2 * j + 1];
    if (v) atomicOr(&g_i32flag, 1);
}

__global__ void k_gate(const void* __restrict__ idx_raw, const float* __restrict__ probs) {
    int t = blockIdx.x * blockDim.x + threadIdx.x;
    if (t >= T_TOK) return;
    int e0, e1;
    if (g_i32flag) {
        const int* p = (const int*)idx_raw;
        e0 = p[2 * t]; e1 = p[2 * t + 1];
    } else {
        const long long* p = (const long long*)idx_raw;
        e0 = (int)p[2 * t]; e1 = (int)p[2 * t + 1];
    }
    float p0 = probs[2 * t], p1 = probs[2 * t + 1];
    if (e0 == e1) { p0 = fmaxf(p0, p1); e1 = -1; }   // max over k dedups
    if ((unsigned)e0 < NEXP) {
        int pos = atomicAdd(&g_cnt[e0], 1);
        g_list[e0 * T_TOK + pos] = t;
        g_gval[e0 * T_TOK + pos] = p0;
    }
    if ((unsigned)e1 < NEXP) {
        int pos = atomicAdd(&g_cnt[e1], 1);
        g_list[e1 * T_TOK + pos] = t;
        g_gval[e1 * T_TOK + pos] = p1;
    }
}

__global__ void k_prefix() {
    int s = 0;
    for (int e = 0; e < NEXP; ++e) { g_base[e] = s; s += g_cnt[e]; }
}

// ---------------- prep: tf32-round W1, W2, x into scratch -------------------
__device__ __forceinline__ float4 rnd4(float4 v) {
    v.x = tf32r(v.x); v.y = tf32r(v.y); v.z = tf32r(v.z); v.w = tf32r(v.w);
    return v;
}
__global__ void k_prep(const float4* __restrict__ w1, const float4* __restrict__ w2,
                       const float4* __restrict__ x) {
    const int stride = gridDim.x * blockDim.x;
    float4* o1 = (float4*)g_w1r;
    float4* o2 = (float4*)g_w2r;
    float4* ox = (float4*)g_xr;
    int i0 = blockIdx.x * blockDim.x + threadIdx.x;
    for (int j = i0; j < WELEM / 4; j += stride) {
        o1[j] = rnd4(w1[j]);
        o2[j] = rnd4(w2[j]);
    }
    for (int j = i0; j < (T_TOK * HDIM) / 4; j += stride)
        ox[j] = rnd4(x[j]);
}

// ---------------- grouped GEMM: cp.async 4-stage + ldmatrix fragments -------
// G1: H[base+m, n] = tf32( gelu( xr[list[m]] . W1r[e][n] ) ),  KDIM = HDIM
// G2: out[list[m]] += gate[m] * ( H[base+m] . W2r[e][n] ),      KDIM = HFF
extern __shared__ char dynsm[];

template <int KDIM, bool IS_G1>
__global__ __launch_bounds__(NTHR, 2)
void k_gemm(float* __restrict__ outp) {
    const int e = blockIdx.z;
    const int cnt = g_cnt[e];
    const int m0 = blockIdx.x * BM;
    if (m0 >= cnt) return;
    const int n0 = blockIdx.y * BN;
    const int base = g_base[e];

    const int tid = threadIdx.x;
    const int lane = tid & 31, warp = tid >> 5;
    const int wm = warp & 1, wn = warp >> 1;
    const int g = lane >> 2, tq = lane & 3;
    const uint32_t sb = smem_u32(dynsm);

    const float* Bw = IS_G1 ? g_w1r : g_w2r;

    // ---- cp.async mapping: 1024 granules/stage (A 512 + B 512), 4/thread ----
    const float* srcp[4];
    uint32_t dsto[4];
#pragma unroll
    for (int i = 0; i < 4; ++i) {
        int id = tid + i * NTHR;          // 0..1023
        int isB = id >> 9;                // 0: A rows, 1: B rows
        int r = (id >> 2) & 127;
        int gc = id & 3;
        dsto[i] = (uint32_t)(isB * ABYTES + r * (ROWW * 4) + gc * 16);
        if (isB) {
            srcp[i] = Bw + (size_t)e * HFF * HDIM + (size_t)(n0 + r) * KDIM + gc * 4;
        } else if (IS_G1) {
            int m = m0 + r;
            int tok = (m < cnt) ? g_list[e * T_TOK + m] : g_list[e * T_TOK];
            srcp[i] = g_xr + (size_t)tok * KDIM + gc * 4;
        } else {
            srcp[i] = g_hbuf + (size_t)(base + m0 + r) * KDIM + gc * 4;  // padded
        }
    }

    // ---- ldmatrix per-thread base offsets (bytes within a stage) ----
    // A tiles: rows rb + (lane&15), 16B col = 4*(lane>>4) floats
    const uint32_t aoff =
        (uint32_t)(((wm * 64 + (lane & 15)) * ROWW + 4 * (lane >> 4)) * 4);
    // B tiles: rows wn*32 + 8*(lane>>4) + (lane&7), 16B col = 4*((lane>>3)&1)
    const uint32_t boff = (uint32_t)(ABYTES +
        ((wn * 32 + 8 * (lane >> 4) + (lane & 7)) * ROWW + 4 * ((lane >> 3) & 1)) * 4);

    float acc[4][4][4];
#pragma unroll
    for (int mi = 0; mi < 4; ++mi)
#pragma unroll
        for (int ni = 0; ni < 4; ++ni)
#pragma unroll
            for (int ci = 0; ci < 4; ++ci) acc[mi][ni][ci] = 0.f;

    auto issue = [&](int kt, int buf) {
        uint32_t b = sb + buf * STAGE_BYTES;
#pragma unroll
        for (int i = 0; i < 4; ++i)
            CP_ASYNC16(b + dsto[i], srcp[i] + kt * KC);
        CP_COMMIT();
    };

    constexpr int KT = KDIM / KC;
    issue(0, 0);
    issue(1, 1);
    issue(2, 2);

    for (int kt = 0; kt < KT; ++kt) {
        // committed-but-pending after this wait must exclude group kt
        const int rem = KT - 1 - kt;
        if (rem >= 2)       asm volatile("cp.async.wait_group 2;" ::: "memory");
        else if (rem == 1)  asm volatile("cp.async.wait_group 1;" ::: "memory");
        else                asm volatile("cp.async.wait_group 0;" ::: "memory");
        __syncthreads();   // stage kt landed for ALL threads; buffer (kt-1)%4 free
        if (kt + 3 < KT) issue(kt + 3, (kt + 3) & 3);

        const uint32_t stg = sb + (kt & 3) * STAGE_BYTES;
#pragma unroll
        for (int ks = 0; ks < 2; ++ks) {
            uint32_t aF[4][4], bF[4][2];
#pragma unroll
            for (int mi = 0; mi < 4; ++mi)
                LDSM_X4(aF[mi][0], aF[mi][1], aF[mi][2], aF[mi][3],
                        stg + aoff + (uint32_t)((mi * 16 * ROWW + ks * 8) * 4));
            LDSM_X4(bF[0][0], bF[0][1], bF[1][0], bF[1][1],
                    stg + boff + (uint32_t)(ks * 8 * 4));
            LDSM_X4(bF[2][0], bF[2][1], bF[3][0], bF[3][1],
                    stg + boff + (uint32_t)((16 * ROWW + ks * 8) * 4));
#pragma unroll
            for (int mi = 0; mi < 4; ++mi)
#pragma unroll
                for (int ni = 0; ni < 4; ++ni)
                    MMA_TF32(acc[mi][ni], aF[mi], bF[ni]);
        }
        // no bottom barrier: buffer kt%4 is only rewritten after the top
        // barrier of iteration kt+1, which all warps reach post-compute.
    }

    // ---- epilogue (identical to round 10) ----
#pragma unroll
    for (int mi = 0; mi < 4; ++mi) {
        const int mA = m0 + wm * 64 + mi * 16 + g;
        const int mB = mA + 8;
        if (IS_G1) {
            float* rowA = g_hbuf + (size_t)(base + mA) * HFF;
            float* rowB = g_hbuf + (size_t)(base + mB) * HFF;
#pragma unroll
            for (int ni = 0; ni < 4; ++ni) {
                const int col = n0 + wn * 32 + ni * 8 + 2 * tq;
                if (mA < cnt) {
                    float2 v;
                    v.x = tf32r(gelu_t(acc[mi][ni][0]));
                    v.y = tf32r(gelu_t(acc[mi][ni][1]));
                    *(float2*)(rowA + col) = v;
                }
                if (mB < cnt) {
                    float2 v;
                    v.x = tf32r(gelu_t(acc[mi][ni][2]));
                    v.y = tf32r(gelu_t(acc[mi][ni][3]));
                    *(float2*)(rowB + col) = v;
                }
            }
        } else {
            int tokA = 0, tokB = 0;
            float gA = 0.f, gB = 0.f;
            if (mA < cnt) { tokA = g_list[e * T_TOK + mA]; gA = g_gval[e * T_TOK + mA]; }
            if (mB < cnt) { tokB = g_list[e * T_TOK + mB]; gB = g_gval[e * T_TOK + mB]; }
#pragma unroll
            for (int ni = 0; ni < 4; ++ni) {
                const int col = n0 + wn * 32 + ni * 8 + 2 * tq;
                if (mA < cnt) {
                    atomicAdd(&outp[(size_t)tokA * HDIM + col],     gA * acc[mi][ni][0]);
                    atomicAdd(&outp[(size_t)tokA * HDIM + col + 1], gA * acc[mi][ni][1]);
                }
                if (mB < cnt) {
                    atomicAdd(&outp[(size_t)tokB * HDIM + col],     gB * acc[mi][ni][2]);
                    atomicAdd(&outp[(size_t)tokB * HDIM + col + 1], gB * acc[mi][ni][3]);
                }
            }
        }
    }
}

// ---------------- launch ----------------
extern "C" void kernel_launch(void* const* d_in, const int* in_sizes, int n_in,
                              void* d_out, int out_size) {
    const float* x     = (const float*)d_in[0];
    const float* probs = (const float*)d_in[1];
    const void*  idx   = d_in[2];
    const float* W1    = (const float*)d_in[3];
    const float* W2    = (const float*)d_in[4];
    float* out = (float*)d_out;

    cudaFuncSetAttribute(k_gemm<HDIM, true>,
                         cudaFuncAttributeMaxDynamicSharedMemorySize, DYN_SMEM);
    cudaFuncSetAttribute(k_gemm<HFF, false>,
                         cudaFuncAttributeMaxDynamicSharedMemorySize, DYN_SMEM);

    const int n4 = out_size / 4;
    k_zero<<<(n4 + 255) / 256, 256>>>((float4*)out, n4);
    k_detect<<<32, 256>>>((const int*)idx);
    k_gate<<<(T_TOK + 255) / 256, 256>>>(idx, probs);
    k_prefix<<<1, 1>>>();
    k_prep<<<1024, 256>>>((const float4*)W1, (const float4*)W2, (const float4*)x);

    dim3 g1(T_TOK / BM, HFF / BN, NEXP);   // (32, 32, 8); tail CTAs self-prune
    k_gemm<HDIM, true><<<g1, NTHR, DYN_SMEM>>>(nullptr);

    dim3 g2(T_TOK / BM, HDIM / BN, NEXP);  // (32, 8, 8)
    k_gemm<HFF, false><<<g2, NTHR, DYN_SMEM>>>(out);
}

// round 12
// speedup vs baseline: 1.6011x; 1.1009x over previous
#include <cuda_runtime.h>
#include <cstdint>

// ---------------- problem constants ----------------
#define T_TOK 4096      // B*S
#define HDIM  1024
#define HFF   4096
#define NEXP  8
#define WELEM (NEXP * HFF * HDIM)     // 33554432 floats per weight tensor

// ---------------- GEMM tiling ----------------
#define BM 128
#define BN 128
#define KC 32                          // K per pipeline chunk (4 k-steps of 8)
#define NSTAGE 3
#define ROWW 36                        // padded smem row stride in floats (144B = 9 x 16B)
#define ABYTES (BM * ROWW * 4)         // 18432 B per operand per stage
#define STAGE_BYTES (2 * ABYTES)       // 36864 B
#define DYN_SMEM (NSTAGE * STAGE_BYTES) // 110592 B -> 2 CTAs/SM
#define NTHR 256

// ---------------- device scratch (no allocations allowed) ----------------
__device__ int   g_cnt[NEXP];
__device__ int   g_base[NEXP];
__device__ int   g_list[NEXP * T_TOK];
__device__ float g_gval[NEXP * T_TOK];
__device__ int   g_i32flag;
__device__ __align__(16) float g_xr[T_TOK * HDIM];        // tf32-rounded x
__device__ __align__(16) float g_w1r[WELEM];              // tf32-rounded W1
__device__ __align__(16) float g_w2r[WELEM];              // tf32-rounded W2
// H rows (already tf32-rounded); padded by BM rows so tail tiles of the last
// expert can be READ (never written) without OOB.
__device__ __align__(16) float g_hbuf[(size_t)(T_TOK * 2 + BM) * HFF];

// ---------------- helpers ----------------
__device__ __forceinline__ uint32_t smem_u32(const void* p) {
    uint32_t a;
    asm("{ .reg .u64 t; cvta.to.shared.u64 t, %1; cvt.u32.u64 %0, t; }" : "=r"(a) : "l"(p));
    return a;
}
__device__ __forceinline__ float tf32r(float x) {
    uint32_t o;
    asm("cvt.rna.tf32.f32 %0, %1;" : "=r"(o) : "f"(x));
    return __uint_as_float(o);
}
__device__ __forceinline__ float gelu_t(float x) {
    float t = tanhf(0.7978845608028654f * (x + 0.044715f * x * x * x));
    return 0.5f * x * (1.0f + t);
}

#define MMA_TF32(c, a, b)                                                   \
    asm volatile(                                                           \
        "mma.sync.aligned.m16n8k8.row.col.f32.tf32.tf32.f32 "               \
        "{%0,%1,%2,%3}, {%4,%5,%6,%7}, {%8,%9}, {%0,%1,%2,%3};"             \
        : "+f"((c)[0]), "+f"((c)[1]), "+f"((c)[2]), "+f"((c)[3])            \
        : "r"((a)[0]), "r"((a)[1]), "r"((a)[2]), "r"((a)[3]),               \
          "r"((b)[0]), "r"((b)[1]))

#define CP_ASYNC16(dst, src)                                                \
    asm volatile("cp.async.cg.shared.global [%0], [%1], 16;"                \
                 :: "r"(dst), "l"(src) : "memory")
#define CP_COMMIT()  asm volatile("cp.async.commit_group;" ::: "memory")

// ldmatrix x4: reg k = 8x8-b16 tile k; thread holds the 32-bit element at
// (row = lane>>2, col = lane&3) of its tile — exactly the tf32 mma fragment.
#define LDSM_X4(r0, r1, r2, r3, addr)                                       \
    asm volatile("ldmatrix.sync.aligned.m8n8.x4.shared.b16 {%0,%1,%2,%3}, [%4];" \
        : "=r"(r0), "=r"(r1), "=r"(r2), "=r"(r3) : "r"(addr))

// ---------------- small kernels (validated rounds 3-11) ----------------
__global__ void k_zero(float4* out4, int n4) {
    int i = blockIdx.x * blockDim.x + threadIdx.x;
    if (i < n4) out4[i] = make_float4(0.f, 0.f, 0.f, 0.f);
    if (i < NEXP) g_cnt[i] = 0;
    if (i == 0) g_i32flag = 0;
}

__global__ void k_detect(const int* __restrict__ idx32) {
    int i = blockIdx.x * blockDim.x + threadIdx.x;
    int v = 0;
    for (int j = i; j < (T_TOK * 2) / 2; j += gridDim.x * blockDim.x)
        v |= idx32[2 * j + 1];
    if (v) atomicOr(&g_i32flag, 1);
}

__global__ void k_gate(const void* __restrict__ idx_raw, const float* __restrict__ probs) {
    int t = blockIdx.x * blockDim.x + threadIdx.x;
    if (t >= T_TOK) return;
    int e0, e1;
    if (g_i32flag) {
        const int* p = (const int*)idx_raw;
        e0 = p[2 * t]; e1 = p[2 * t + 1];
    } else {
        const long long* p = (const long long*)idx_raw;
        e0 = (int)p[2 * t]; e1 = (int)p[2 * t + 1];
    }
    float p0 = probs[2 * t], p1 = probs[2 * t + 1];
    if (e0 == e1) { p0 = fmaxf(p0, p1); e1 = -1; }   // max over k dedups
    if ((unsigned)e0 < NEXP) {
        int pos = atomicAdd(&g_cnt[e0], 1);
        g_list[e0 * T_TOK + pos] = t;
        g_gval[e0 * T_TOK + pos] = p0;
    }
    if ((unsigned)e1 < NEXP) {
        int pos = atomicAdd(&g_cnt[e1], 1);
        g_list[e1 * T_TOK + pos] = t;
        g_gval[e1 * T_TOK + pos] = p1;
    }
}

__global__ void k_prefix() {
    int s = 0;
    for (int e = 0; e < NEXP; ++e) { g_base[e] = s; s += g_cnt[e]; }
}

// ---------------- prep: tf32-round W1, W2, x into scratch -------------------
__device__ __forceinline__ float4 rnd4(float4 v) {
    v.x = tf32r(v.x); v.y = tf32r(v.y); v.z = tf32r(v.z); v.w = tf32r(v.w);
    return v;
}
__global__ void k_prep(const float4* __restrict__ w1, const float4* __restrict__ w2,
                       const float4* __restrict__ x) {
    const int stride = gridDim.x * blockDim.x;
    float4* o1 = (float4*)g_w1r;
    float4* o2 = (float4*)g_w2r;
    float4* ox = (float4*)g_xr;
    int i0 = blockIdx.x * blockDim.x + threadIdx.x;
    for (int j = i0; j < WELEM / 4; j += stride) {
        o1[j] = rnd4(w1[j]);
        o2[j] = rnd4(w2[j]);
    }
    for (int j = i0; j < (T_TOK * HDIM) / 4; j += stride)
        ox[j] = rnd4(x[j]);
}

// ---------------- grouped GEMM: cp.async 3-stage, KC=32, ldmatrix ----------
// G1: H[base+m, n] = tf32( gelu( xr[list[m]] . W1r[e][n] ) ),  KDIM = HDIM
// G2: out[list[m]] += gate[m] * ( H[base+m] . W2r[e][n] ),      KDIM = HFF
extern __shared__ char dynsm[];

template <int KDIM, bool IS_G1>
__global__ __launch_bounds__(NTHR, 2)
void k_gemm(float* __restrict__ outp) {
    const int e = blockIdx.z;
    const int cnt = g_cnt[e];
    const int m0 = blockIdx.x * BM;
    if (m0 >= cnt) return;
    const int n0 = blockIdx.y * BN;
    const int base = g_base[e];

    const int tid = threadIdx.x;
    const int lane = tid & 31, warp = tid >> 5;
    const int wm = warp & 1, wn = warp >> 1;
    const int g = lane >> 2, tq = lane & 3;
    const uint32_t sb = smem_u32(dynsm);

    const float* Bw = IS_G1 ? g_w1r : g_w2r;

    // ---- cp.async mapping: 2048 granules/stage (A 1024 + B 1024), 8/thread --
    const float* srcp[8];
    uint32_t dsto[8];
#pragma unroll
    for (int i = 0; i < 8; ++i) {
        int id = tid + i * NTHR;          // 0..2047
        int isB = id >> 10;               // 0: A rows, 1: B rows
        int r = (id >> 3) & 127;
        int gc = id & 7;                  // 16B granule within 128B row
        dsto[i] = (uint32_t)(isB * ABYTES + r * (ROWW * 4) + gc * 16);
        if (isB) {
            srcp[i] = Bw + (size_t)e * HFF * HDIM + (size_t)(n0 + r) * KDIM + gc * 4;
        } else if (IS_G1) {
            int m = m0 + r;
            int tok = (m < cnt) ? g_list[e * T_TOK + m] : g_list[e * T_TOK];
            srcp[i] = g_xr + (size_t)tok * KDIM + gc * 4;
        } else {
            srcp[i] = g_hbuf + (size_t)(base + m0 + r) * KDIM + gc * 4;  // padded
        }
    }

    // ---- ldmatrix per-thread base offsets (bytes within a stage) ----
    // A tiles: rows rb + (lane&15), 16B col = 4*(lane>>4) floats
    const uint32_t aoff =
        (uint32_t)(((wm * 64 + (lane & 15)) * ROWW + 4 * (lane >> 4)) * 4);
    // B tiles: rows wn*32 + 8*(lane>>4) + (lane&7), 16B col = 4*((lane>>3)&1)
    const uint32_t boff = (uint32_t)(ABYTES +
        ((wn * 32 + 8 * (lane >> 4) + (lane & 7)) * ROWW + 4 * ((lane >> 3) & 1)) * 4);

    float acc[4][4][4];
#pragma unroll
    for (int mi = 0; mi < 4; ++mi)
#pragma unroll
        for (int ni = 0; ni < 4; ++ni)
#pragma unroll
            for (int ci = 0; ci < 4; ++ci) acc[mi][ni][ci] = 0.f;

    auto issue = [&](int kt, int buf) {
        uint32_t b = sb + buf * STAGE_BYTES;
#pragma unroll
        for (int i = 0; i < 8; ++i)
            CP_ASYNC16(b + dsto[i], srcp[i] + kt * KC);
        CP_COMMIT();
    };

    constexpr int KT = KDIM / KC;
    issue(0, 0);
    issue(1, 1);

    uint32_t aF[2][4][4], bF[2][4][2];
    auto ldfrag = [&](int pb, uint32_t stg, int ks) {
#pragma unroll
        for (int mi = 0; mi < 4; ++mi)
            LDSM_X4(aF[pb][mi][0], aF[pb][mi][1], aF[pb][mi][2], aF[pb][mi][3],
                    stg + aoff + (uint32_t)((mi * 16 * ROWW + ks * 8) * 4));
        LDSM_X4(bF[pb][0][0], bF[pb][0][1], bF[pb][1][0], bF[pb][1][1],
                stg + boff + (uint32_t)(ks * 8 * 4));
        LDSM_X4(bF[pb][2][0], bF[pb][2][1], bF[pb][3][0], bF[pb][3][1],
                stg + boff + (uint32_t)((16 * ROWW + ks * 8) * 4));
    };

    for (int kt = 0; kt < KT; ++kt) {
        // after this wait, committed-but-pending must exclude group kt
        if (kt < KT - 1) asm volatile("cp.async.wait_group 1;" ::: "memory");
        else             asm volatile("cp.async.wait_group 0;" ::: "memory");
        __syncthreads();   // stage kt landed for ALL threads; buffer (kt-1)%3 free
        if (kt + 2 < KT) issue(kt + 2, (kt + 2) % 3);

        const uint32_t stg = sb + (kt % 3) * STAGE_BYTES;
        ldfrag(0, stg, 0);
#pragma unroll
        for (int ks = 0; ks < 4; ++ks) {
            const int pb = ks & 1;
            if (ks < 3) ldfrag(pb ^ 1, stg, ks + 1);  // hide LDS under MMAs
#pragma unroll
            for (int mi = 0; mi < 4; ++mi)
#pragma unroll
                for (int ni = 0; ni < 4; ++ni)
                    MMA_TF32(acc[mi][ni], aF[pb][mi], bF[pb][ni]);
        }
        // no bottom barrier: buffer kt%3 is only rewritten after the top
        // barrier of iteration kt+1, which all warps reach post-compute.
    }

    // ---- epilogue (identical to rounds 10-11) ----
#pragma unroll
    for (int mi = 0; mi < 4; ++mi) {
        const int mA = m0 + wm * 64 + mi * 16 + g;
        const int mB = mA + 8;
        if (IS_G1) {
            float* rowA = g_hbuf + (size_t)(base + mA) * HFF;
            float* rowB = g_hbuf + (size_t)(base + mB) * HFF;
#pragma unroll
            for (int ni = 0; ni < 4; ++ni) {
                const int col = n0 + wn * 32 + ni * 8 + 2 * tq;
                if (mA < cnt) {
                    float2 v;
                    v.x = tf32r(gelu_t(acc[mi][ni][0]));
                    v.y = tf32r(gelu_t(acc[mi][ni][1]));
                    *(float2*)(rowA + col) = v;
                }
                if (mB < cnt) {
                    float2 v;
                    v.x = tf32r(gelu_t(acc[mi][ni][2]));
                    v.y = tf32r(gelu_t(acc[mi][ni][3]));
                    *(float2*)(rowB + col) = v;
                }
            }
        } else {
            int tokA = 0, tokB = 0;
            float gA = 0.f, gB = 0.f;
            if (mA < cnt) { tokA = g_list[e * T_TOK + mA]; gA = g_gval[e * T_TOK + mA]; }
            if (mB < cnt) { tokB = g_list[e * T_TOK + mB]; gB = g_gval[e * T_TOK + mB]; }
#pragma unroll
            for (int ni = 0; ni < 4; ++ni) {
                const int col = n0 + wn * 32 + ni * 8 + 2 * tq;
                if (mA < cnt) {
                    atomicAdd(&outp[(size_t)tokA * HDIM + col],     gA * acc[mi][ni][0]);
                    atomicAdd(&outp[(size_t)tokA * HDIM + col + 1], gA * acc[mi][ni][1]);
                }
                if (mB < cnt) {
                    atomicAdd(&outp[(size_t)tokB * HDIM + col],     gB * acc[mi][ni][2]);
                    atomicAdd(&outp[(size_t)tokB * HDIM + col + 1], gB * acc[mi][ni][3]);
                }
            }
        }
    }
}

// ---------------- launch ----------------
extern "C" void kernel_launch(void* const* d_in, const int* in_sizes, int n_in,
                              void* d_out, int out_size) {
    const float* x     = (const float*)d_in[0];
    const float* probs = (const float*)d_in[1];
    const void*  idx   = d_in[2];
    const float* W1    = (const float*)d_in[3];
    const float* W2    = (const float*)d_in[4];
    float* out = (float*)d_out;

    cudaFuncSetAttribute(k_gemm<HDIM, true>,
                         cudaFuncAttributeMaxDynamicSharedMemorySize, DYN_SMEM);
    cudaFuncSetAttribute(k_gemm<HFF, false>,
                         cudaFuncAttributeMaxDynamicSharedMemorySize, DYN_SMEM);

    const int n4 = out_size / 4;
    k_zero<<<(n4 + 255) / 256, 256>>>((float4*)out, n4);
    k_detect<<<32, 256>>>((const int*)idx);
    k_gate<<<(T_TOK + 255) / 256, 256>>>(idx, probs);
    k_prefix<<<1, 1>>>();
    k_prep<<<1024, 256>>>((const float4*)W1, (const float4*)W2, (const float4*)x);

    dim3 g1(T_TOK / BM, HFF / BN, NEXP);   // (32, 32, 8); tail CTAs self-prune
    k_gemm<HDIM, true><<<g1, NTHR, DYN_SMEM>>>(nullptr);

    dim3 g2(T_TOK / BM, HDIM / BN, NEXP);  // (32, 8, 8)
    k_gemm<HFF, false><<<g2, NTHR, DYN_SMEM>>>(out);
}

// round 13
// speedup vs baseline: 1.6629x; 1.0386x over previous
#include <cuda_runtime.h>
#include <cstdint>

// ---------------- problem constants ----------------
#define T_TOK 4096      // B*S
#define HDIM  1024
#define HFF   4096
#define NEXP  8

// ---------------- GEMM tiling ----------------
#define BM 128
#define BN 128
#define KC 32                          // K per pipeline chunk (4 k-steps of 8)
#define NSTAGE 3
#define ROWW 36                        // padded smem row stride in floats (144B = 9 x 16B)
#define ABYTES (BM * ROWW * 4)         // 18432 B per operand per stage
#define STAGE_BYTES (2 * ABYTES)       // 36864 B
#define DYN_SMEM (NSTAGE * STAGE_BYTES) // 110592 B -> 2 CTAs/SM
#define NTHR 256

// ---------------- device scratch (no allocations allowed) ----------------
__device__ int   g_cnt[NEXP];
__device__ int   g_list[NEXP * T_TOK];
__device__ float g_gval[NEXP * T_TOK];
__device__ int   g_i32flag;
__device__ __align__(16) float g_xr[T_TOK * HDIM];        // tf32-rounded x
// H rows (already tf32-rounded); padded by BM rows so tail tiles of the last
// expert can be READ (never written) without OOB.
__device__ __align__(16) float g_hbuf[(size_t)(T_TOK * 2 + BM) * HFF];

// ---------------- helpers ----------------
__device__ __forceinline__ uint32_t smem_u32(const void* p) {
    uint32_t a;
    asm("{ .reg .u64 t; cvta.to.shared.u64 t, %1; cvt.u32.u64 %0, t; }" : "=r"(a) : "l"(p));
    return a;
}
__device__ __forceinline__ float tf32r(float x) {
    uint32_t o;
    asm("cvt.rna.tf32.f32 %0, %1;" : "=r"(o) : "f"(x));
    return __uint_as_float(o);
}
__device__ __forceinline__ uint32_t tf32r_u(uint32_t xu) {
    uint32_t o;
    asm("cvt.rna.tf32.f32 %0, %1;" : "=r"(o) : "f"(__uint_as_float(xu)));
    return o;
}
__device__ __forceinline__ float gelu_t(float x) {
    float t = tanhf(0.7978845608028654f * (x + 0.044715f * x * x * x));
    return 0.5f * x * (1.0f + t);
}

#define MMA_TF32(c, a, b)                                                   \
    asm volatile(                                                           \
        "mma.sync.aligned.m16n8k8.row.col.f32.tf32.tf32.f32 "               \
        "{%0,%1,%2,%3}, {%4,%5,%6,%7}, {%8,%9}, {%0,%1,%2,%3};"             \
        : "+f"((c)[0]), "+f"((c)[1]), "+f"((c)[2]), "+f"((c)[3])            \
        : "r"((a)[0]), "r"((a)[1]), "r"((a)[2]), "r"((a)[3]),               \
          "r"((b)[0]), "r"((b)[1]))

#define CP_ASYNC16(dst, src)                                                \
    asm volatile("cp.async.cg.shared.global [%0], [%1], 16;"                \
                 :: "r"(dst), "l"(src) : "memory")
#define CP_COMMIT()  asm volatile("cp.async.commit_group;" ::: "memory")

// ldmatrix x4: reg k = 8x8-b16 tile k; thread holds the 32-bit element at
// (row = lane>>2, col = lane&3) of its tile — exactly the tf32 mma fragment.
#define LDSM_X4(r0, r1, r2, r3, addr)                                       \
    asm volatile("ldmatrix.sync.aligned.m8n8.x4.shared.b16 {%0,%1,%2,%3}, [%4];" \
        : "=r"(r0), "=r"(r1), "=r"(r2), "=r"(r3) : "r"(addr))

// ---------------- small kernels (validated rounds 3-12) ----------------
__global__ void k_zero(float4* out4, int n4) {
    int i = blockIdx.x * blockDim.x + threadIdx.x;
    if (i < n4) out4[i] = make_float4(0.f, 0.f, 0.f, 0.f);
    if (i < NEXP) g_cnt[i] = 0;
    if (i == 0) g_i32flag = 0;
}

__global__ void k_detect(const int* __restrict__ idx32) {
    int i = blockIdx.x * blockDim.x + threadIdx.x;
    int v = 0;
    for (int j = i; j < (T_TOK * 2) / 2; j += gridDim.x * blockDim.x)
        v |= idx32[2 * j + 1];
    if (v) atomicOr(&g_i32flag, 1);
}

__global__ void k_gate(const void* __restrict__ idx_raw, const float* __restrict__ probs) {
    int t = blockIdx.x * blockDim.x + threadIdx.x;
    if (t >= T_TOK) return;
    int e0, e1;
    if (g_i32flag) {
        const int* p = (const int*)idx_raw;
        e0 = p[2 * t]; e1 = p[2 * t + 1];
    } else {
        const long long* p = (const long long*)idx_raw;
        e0 = (int)p[2 * t]; e1 = (int)p[2 * t + 1];
    }
    float p0 = probs[2 * t], p1 = probs[2 * t + 1];
    if (e0 == e1) { p0 = fmaxf(p0, p1); e1 = -1; }   // max over k dedups
    if ((unsigned)e0 < NEXP) {
        int pos = atomicAdd(&g_cnt[e0], 1);
        g_list[e0 * T_TOK + pos] = t;
        g_gval[e0 * T_TOK + pos] = p0;
    }
    if ((unsigned)e1 < NEXP) {
        int pos = atomicAdd(&g_cnt[e1], 1);
        g_list[e1 * T_TOK + pos] = t;
        g_gval[e1 * T_TOK + pos] = p1;
    }
}

// ---------------- prep: tf32-round x only (weights round in-register) -------
__global__ void k_prepx(const float4* __restrict__ x) {
    const int stride = gridDim.x * blockDim.x;
    float4* ox = (float4*)g_xr;
    for (int j = blockIdx.x * blockDim.x + threadIdx.x;
         j < (T_TOK * HDIM) / 4; j += stride) {
        float4 v = x[j];
        v.x = tf32r(v.x); v.y = tf32r(v.y); v.z = tf32r(v.z); v.w = tf32r(v.w);
        ox[j] = v;
    }
}

// ---------------- grouped GEMM: cp.async 3-stage, KC=32, ldmatrix ----------
// G1: H[base+m, n] = tf32( gelu( xr[list[m]] . rna(W1[e][n]) ) ),  KDIM = HDIM
// G2: out[list[m]] += gate[m] * ( H[base+m] . rna(W2[e][n]) ),      KDIM = HFF
// B operands are raw fp32 from the harness buffers; rna-rounded per-fragment
// after ldmatrix — bitwise identical to pre-rounding in memory.
extern __shared__ char dynsm[];

template <int KDIM, bool IS_G1>
__global__ __launch_bounds__(NTHR, 2)
void k_gemm(const float* __restrict__ Bsrc, float* __restrict__ outp) {
    const int e = blockIdx.z;
    const int cnt = g_cnt[e];
    const int m0 = blockIdx.x * BM;
    if (m0 >= cnt) return;
    const int n0 = blockIdx.y * BN;
    int base = 0;
#pragma unroll
    for (int i = 0; i < NEXP; ++i) base += (i < e) ? g_cnt[i] : 0;

    const int tid = threadIdx.x;
    const int lane = tid & 31, warp = tid >> 5;
    const int wm = warp & 1, wn = warp >> 1;
    const int g = lane >> 2, tq = lane & 3;
    const uint32_t sb = smem_u32(dynsm);

    // ---- cp.async mapping: 2048 granules/stage (A 1024 + B 1024), 8/thread --
    const float* srcp[8];
    uint32_t dsto[8];
#pragma unroll
    for (int i = 0; i < 8; ++i) {
        int id = tid + i * NTHR;          // 0..2047
        int isB = id >> 10;               // 0: A rows, 1: B rows
        int r = (id >> 3) & 127;
        int gc = id & 7;                  // 16B granule within 128B row
        dsto[i] = (uint32_t)(isB * ABYTES + r * (ROWW * 4) + gc * 16);
        if (isB) {
            srcp[i] = Bsrc + (size_t)e * HFF * HDIM + (size_t)(n0 + r) * KDIM + gc * 4;
        } else if (IS_G1) {
            int m = m0 + r;
            int tok = (m < cnt) ? g_list[e * T_TOK + m] : g_list[e * T_TOK];
            srcp[i] = g_xr + (size_t)tok * KDIM + gc * 4;
        } else {
            srcp[i] = g_hbuf + (size_t)(base + m0 + r) * KDIM + gc * 4;  // padded
        }
    }

    // ---- ldmatrix per-thread base offsets (bytes within a stage) ----
    const uint32_t aoff =
        (uint32_t)(((wm * 64 + (lane & 15)) * ROWW + 4 * (lane >> 4)) * 4);
    const uint32_t boff = (uint32_t)(ABYTES +
        ((wn * 32 + 8 * (lane >> 4) + (lane & 7)) * ROWW + 4 * ((lane >> 3) & 1)) * 4);

    float acc[4][4][4];
#pragma unroll
    for (int mi = 0; mi < 4; ++mi)
#pragma unroll
        for (int ni = 0; ni < 4; ++ni)
#pragma unroll
            for (int ci = 0; ci < 4; ++ci) acc[mi][ni][ci] = 0.f;

    auto issue = [&](int kt, int buf) {
        uint32_t b = sb + buf * STAGE_BYTES;
#pragma unroll
        for (int i = 0; i < 8; ++i)
            CP_ASYNC16(b + dsto[i], srcp[i] + kt * KC);
        CP_COMMIT();
    };

    constexpr int KT = KDIM / KC;
    issue(0, 0);
    issue(1, 1);

    uint32_t aF[2][4][4], bF[2][4][2];
    auto ldfrag = [&](int pb, uint32_t stg, int ks) {
#pragma unroll
        for (int mi = 0; mi < 4; ++mi)
            LDSM_X4(aF[pb][mi][0], aF[pb][mi][1], aF[pb][mi][2], aF[pb][mi][3],
                    stg + aoff + (uint32_t)((mi * 16 * ROWW + ks * 8) * 4));
        LDSM_X4(bF[pb][0][0], bF[pb][0][1], bF[pb][1][0], bF[pb][1][1],
                stg + boff + (uint32_t)(ks * 8 * 4));
        LDSM_X4(bF[pb][2][0], bF[pb][2][1], bF[pb][3][0], bF[pb][3][1],
                stg + boff + (uint32_t)((16 * ROWW + ks * 8) * 4));
        // round raw-fp32 weight fragments to tf32 (rna) — 8 cvts vs 32 MMAs
#pragma unroll
        for (int ni = 0; ni < 4; ++ni) {
            bF[pb][ni][0] = tf32r_u(bF[pb][ni][0]);
            bF[pb][ni][1] = tf32r_u(bF[pb][ni][1]);
        }
    };

    for (int kt = 0; kt < KT; ++kt) {
        // after this wait, committed-but-pending must exclude group kt
        if (kt < KT - 1) asm volatile("cp.async.wait_group 1;" ::: "memory");
        else             asm volatile("cp.async.wait_group 0;" ::: "memory");
        __syncthreads();   // stage kt landed for ALL threads; buffer (kt-1)%3 free
        if (kt + 2 < KT) issue(kt + 2, (kt + 2) % 3);

        const uint32_t stg = sb + (kt % 3) * STAGE_BYTES;
        ldfrag(0, stg, 0);
#pragma unroll
        for (int ks = 0; ks < 4; ++ks) {
            const int pb = ks & 1;
            if (ks < 3) ldfrag(pb ^ 1, stg, ks + 1);  // hide LDS+cvt under MMAs
#pragma unroll
            for (int mi = 0; mi < 4; ++mi)
#pragma unroll
                for (int ni = 0; ni < 4; ++ni)
                    MMA_TF32(acc[mi][ni], aF[pb][mi], bF[pb][ni]);
        }
        // no bottom barrier: buffer kt%3 is only rewritten after the top
        // barrier of iteration kt+1, which all warps reach post-compute.
    }

    // ---- epilogue (identical to rounds 10-12) ----
#pragma unroll
    for (int mi = 0; mi < 4; ++mi) {
        const int mA = m0 + wm * 64 + mi * 16 + g;
        const int mB = mA + 8;
        if (IS_G1) {
            float* rowA = g_hbuf + (size_t)(base + mA) * HFF;
            float* rowB = g_hbuf + (size_t)(base + mB) * HFF;
#pragma unroll
            for (int ni = 0; ni < 4; ++ni) {
                const int col = n0 + wn * 32 + ni * 8 + 2 * tq;
                if (mA < cnt) {
                    float2 v;
                    v.x = tf32r(gelu_t(acc[mi][ni][0]));
                    v.y = tf32r(gelu_t(acc[mi][ni][1]));
                    *(float2*)(rowA + col) = v;
                }
                if (mB < cnt) {
                    float2 v;
                    v.x = tf32r(gelu_t(acc[mi][ni][2]));
                    v.y = tf32r(gelu_t(acc[mi][ni][3]));
                    *(float2*)(rowB + col) = v;
                }
            }
        } else {
            int tokA = 0, tokB = 0;
            float gA = 0.f, gB = 0.f;
            if (mA < cnt) { tokA = g_list[e * T_TOK + mA]; gA = g_gval[e * T_TOK + mA]; }
            if (mB < cnt) { tokB = g_list[e * T_TOK + mB]; gB = g_gval[e * T_TOK + mB]; }
#pragma unroll
            for (int ni = 0; ni < 4; ++ni) {
                const int col = n0 + wn * 32 + ni * 8 + 2 * tq;
                if (mA < cnt) {
                    atomicAdd(&outp[(size_t)tokA * HDIM + col],     gA * acc[mi][ni][0]);
                    atomicAdd(&outp[(size_t)tokA * HDIM + col + 1], gA * acc[mi][ni][1]);
                }
                if (mB < cnt) {
                    atomicAdd(&outp[(size_t)tokB * HDIM + col],     gB * acc[mi][ni][2]);
                    atomicAdd(&outp[(size_t)tokB * HDIM + col + 1], gB * acc[mi][ni][3]);
                }
            }
        }
    }
}

// ---------------- launch ----------------
extern "C" void kernel_launch(void* const* d_in, const int* in_sizes, int n_in,
                              void* d_out, int out_size) {
    const float* x     = (const float*)d_in[0];
    const float* probs = (const float*)d_in[1];
    const void*  idx   = d_in[2];
    const float* W1    = (const float*)d_in[3];
    const float* W2    = (const float*)d_in[4];
    float* out = (float*)d_out;

    cudaFuncSetAttribute(k_gemm<HDIM, true>,
                         cudaFuncAttributeMaxDynamicSharedMemorySize, DYN_SMEM);
    cudaFuncSetAttribute(k_gemm<HFF, false>,
                         cudaFuncAttributeMaxDynamicSharedMemorySize, DYN_SMEM);

    const int n4 = out_size / 4;
    k_zero<<<(n4 + 255) / 256, 256>>>((float4*)out, n4);
    k_detect<<<32, 256>>>((const int*)idx);
    k_gate<<<(T_TOK + 255) / 256, 256>>>(idx, probs);
    k_prepx<<<256, 256>>>((const float4*)x);

    dim3 g1(T_TOK / BM, HFF / BN, NEXP);   // (32, 32, 8); tail CTAs self-prune
    k_gemm<HDIM, true><<<g1, NTHR, DYN_SMEM>>>(W1, nullptr);

    dim3 g2(T_TOK / BM, HDIM / BN, NEXP);  // (32, 8, 8)
    k_gemm<HFF, false><<<g2, NTHR, DYN_SMEM>>>(W2, out);
}

// round 14
// speedup vs baseline: 2.8912x; 1.7386x over previous
#include <cuda_runtime.h>
#include <cuda_fp16.h>
#include <cstdint>

// ---------------- problem constants ----------------
#define T_TOK 4096      // B*S
#define HDIM  1024
#define HFF   4096
#define NEXP  8
#define WELEM (NEXP * HFF * HDIM)     // 33554432 elems per weight tensor

// ---------------- GEMM tiling (fp16 m16n8k16) ----------------
#define BM 128
#define BN 128
#define KC 64                          // K elems per pipeline chunk (4 k-steps of 16)
#define NSTAGE 3
#define ROWB 144                       // padded smem row stride in BYTES (128B data + 16B)
#define ABYTES (BM * ROWB)             // 18432 B per operand per stage
#define STAGE_BYTES (2 * ABYTES)       // 36864 B
#define DYN_SMEM (NSTAGE * STAGE_BYTES) // 110592 B -> 2 CTAs/SM
#define NTHR 256

// ---------------- device scratch (no allocations allowed) ----------------
__device__ int    g_cnt[NEXP];
__device__ int    g_list[NEXP * T_TOK];
__device__ float  g_gval[NEXP * T_TOK];
__device__ int    g_i32flag;
__device__ __align__(16) __half g_xh[T_TOK * HDIM];      // fp16 x
__device__ __align__(16) __half g_w1h[WELEM];            // fp16 W1
__device__ __align__(16) __half g_w2h[WELEM];            // fp16 W2
// fp16 H rows; padded by BM rows so tail tiles of the last expert can be READ
// (never written) without OOB.
__device__ __align__(16) __half g_hbuf[(size_t)(T_TOK * 2 + BM) * HFF];

// ---------------- helpers ----------------
__device__ __forceinline__ uint32_t smem_u32(const void* p) {
    uint32_t a;
    asm("{ .reg .u64 t; cvta.to.shared.u64 t, %1; cvt.u32.u64 %0, t; }" : "=r"(a) : "l"(p));
    return a;
}
__device__ __forceinline__ float gelu_t(float x) {
    float t = tanhf(0.7978845608028654f * (x + 0.044715f * x * x * x));
    return 0.5f * x * (1.0f + t);
}

#define MMA_F16(c, a, b)                                                    \
    asm volatile(                                                           \
        "mma.sync.aligned.m16n8k16.row.col.f32.f16.f16.f32 "                \
        "{%0,%1,%2,%3}, {%4,%5,%6,%7}, {%8,%9}, {%0,%1,%2,%3};"             \
        : "+f"((c)[0]), "+f"((c)[1]), "+f"((c)[2]), "+f"((c)[3])            \
        : "r"((a)[0]), "r"((a)[1]), "r"((a)[2]), "r"((a)[3]),               \
          "r"((b)[0]), "r"((b)[1]))

#define CP_ASYNC16(dst, src)                                                \
    asm volatile("cp.async.cg.shared.global [%0], [%1], 16;"                \
                 :: "r"(dst), "l"(src) : "memory")
#define CP_COMMIT()  asm volatile("cp.async.commit_group;" ::: "memory")

// ldmatrix x4 of 8x8-b16 tiles; with fp16 data the registers are the native
// m16n8k16 fragments (k-pairs packed per 32-bit register).
#define LDSM_X4(r0, r1, r2, r3, addr)                                       \
    asm volatile("ldmatrix.sync.aligned.m8n8.x4.shared.b16 {%0,%1,%2,%3}, [%4];" \
        : "=r"(r0), "=r"(r1), "=r"(r2), "=r"(r3) : "r"(addr))

// ---------------- small kernels (validated rounds 3-13) ----------------
__global__ void k_zero(float4* out4, int n4) {
    int i = blockIdx.x * blockDim.x + threadIdx.x;
    if (i < n4) out4[i] = make_float4(0.f, 0.f, 0.f, 0.f);
    if (i < NEXP) g_cnt[i] = 0;
    if (i == 0) g_i32flag = 0;
}

__global__ void k_detect(const int* __restrict__ idx32) {
    int i = blockIdx.x * blockDim.x + threadIdx.x;
    int v = 0;
    for (int j = i; j < (T_TOK * 2) / 2; j += gridDim.x * blockDim.x)
        v |= idx32[2 * j + 1];
    if (v) atomicOr(&g_i32flag, 1);
}

__global__ void k_gate(const void* __restrict__ idx_raw, const float* __restrict__ probs) {
    int t = blockIdx.x * blockDim.x + threadIdx.x;
    if (t >= T_TOK) return;
    int e0, e1;
    if (g_i32flag) {
        const int* p = (const int*)idx_raw;
        e0 = p[2 * t]; e1 = p[2 * t + 1];
    } else {
        const long long* p = (const long long*)idx_raw;
        e0 = (int)p[2 * t]; e1 = (int)p[2 * t + 1];
    }
    float p0 = probs[2 * t], p1 = probs[2 * t + 1];
    if (e0 == e1) { p0 = fmaxf(p0, p1); e1 = -1; }   // max over k dedups
    if ((unsigned)e0 < NEXP) {
        int pos = atomicAdd(&g_cnt[e0], 1);
        g_list[e0 * T_TOK + pos] = t;
        g_gval[e0 * T_TOK + pos] = p0;
    }
    if ((unsigned)e1 < NEXP) {
        int pos = atomicAdd(&g_cnt[e1], 1);
        g_list[e1 * T_TOK + pos] = t;
        g_gval[e1 * T_TOK + pos] = p1;
    }
}

// ---------------- prep: fp32 -> fp16 copies of W1, W2, x --------------------
__global__ void k_prepw(const float4* __restrict__ w1, const float4* __restrict__ w2) {
    const int stride = gridDim.x * blockDim.x;
    __half2* o1 = (__half2*)g_w1h;
    __half2* o2 = (__half2*)g_w2h;
    for (int j = blockIdx.x * blockDim.x + threadIdx.x; j < WELEM / 4; j += stride) {
        float4 a = w1[j];
        o1[2 * j]     = __floats2half2_rn(a.x, a.y);
        o1[2 * j + 1] = __floats2half2_rn(a.z, a.w);
        float4 b = w2[j];
        o2[2 * j]     = __floats2half2_rn(b.x, b.y);
        o2[2 * j + 1] = __floats2half2_rn(b.z, b.w);
    }
}
__global__ void k_prepx(const float4* __restrict__ x) {
    const int stride = gridDim.x * blockDim.x;
    __half2* ox = (__half2*)g_xh;
    for (int j = blockIdx.x * blockDim.x + threadIdx.x;
         j < (T_TOK * HDIM) / 4; j += stride) {
        float4 v = x[j];
        ox[2 * j]     = __floats2half2_rn(v.x, v.y);
        ox[2 * j + 1] = __floats2half2_rn(v.z, v.w);
    }
}

// ---------------- grouped GEMM: fp16 m16n8k16, cp.async 3-stage -------------
// G1: H[base+m, n] = h16( gelu( xh[list[m]] . W1h[e][n] ) ),  KDIM = HDIM
// G2: out[list[m]] += gate[m] * ( H[base+m] . W2h[e][n] ),     KDIM = HFF
extern __shared__ char dynsm[];

template <int KDIM, bool IS_G1>
__global__ __launch_bounds__(NTHR, 2)
void k_gemm(float* __restrict__ outp) {
    const int e = blockIdx.z;
    const int cnt = g_cnt[e];
    const int m0 = blockIdx.x * BM;
    if (m0 >= cnt) return;
    const int n0 = blockIdx.y * BN;
    int base = 0;
#pragma unroll
    for (int i = 0; i < NEXP; ++i) base += (i < e) ? g_cnt[i] : 0;

    const int tid = threadIdx.x;
    const int lane = tid & 31, warp = tid >> 5;
    const int wm = warp & 1, wn = warp >> 1;
    const int g = lane >> 2, tq = lane & 3;
    const uint32_t sb = smem_u32(dynsm);

    const __half* Bw = IS_G1 ? g_w1h : g_w2h;

    // ---- cp.async mapping: 2048 granules/stage (A 1024 + B 1024), 8/thread --
    // Each row = 128 B = 64 fp16 of K; 8 granules of 16 B.
    const __half* srcp[8];
    uint32_t dsto[8];
#pragma unroll
    for (int i = 0; i < 8; ++i) {
        int id = tid + i * NTHR;          // 0..2047
        int isB = id >> 10;               // 0: A rows, 1: B rows
        int r = (id >> 3) & 127;
        int gc = id & 7;                  // 16B granule (8 fp16) within row
        dsto[i] = (uint32_t)(isB * ABYTES + r * ROWB + gc * 16);
        if (isB) {
            srcp[i] = Bw + (size_t)e * HFF * HDIM + (size_t)(n0 + r) * KDIM + gc * 8;
        } else if (IS_G1) {
            int m = m0 + r;
            int tok = (m < cnt) ? g_list[e * T_TOK + m] : g_list[e * T_TOK];
            srcp[i] = g_xh + (size_t)tok * KDIM + gc * 8;
        } else {
            srcp[i] = g_hbuf + (size_t)(base + m0 + r) * KDIM + gc * 8;  // padded
        }
    }

    // ---- ldmatrix per-thread base offsets (bytes within a stage) ----
    // A m16k16 tile: rows (lane&15), 16B k-half = 16*(lane>>4); +32 B per k-step
    const uint32_t aoff =
        (uint32_t)((wm * 64 + (lane & 15)) * ROWB + 16 * (lane >> 4));
    // B: rows 8*(lane>>4)+(lane&7) (two ni per x4), 16B k-half = 16*((lane>>3)&1)
    const uint32_t boff = (uint32_t)(ABYTES +
        (wn * 32 + 8 * (lane >> 4) + (lane & 7)) * ROWB + 16 * ((lane >> 3) & 1));

    float acc[4][4][4];
#pragma unroll
    for (int mi = 0; mi < 4; ++mi)
#pragma unroll
        for (int ni = 0; ni < 4; ++ni)
#pragma unroll
            for (int ci = 0; ci < 4; ++ci) acc[mi][ni][ci] = 0.f;

    auto issue = [&](int kt, int buf) {
        uint32_t b = sb + buf * STAGE_BYTES;
#pragma unroll
        for (int i = 0; i < 8; ++i)
            CP_ASYNC16(b + dsto[i], srcp[i] + kt * KC);
        CP_COMMIT();
    };

    constexpr int KT = KDIM / KC;
    issue(0, 0);
    issue(1, 1);

    uint32_t aF[2][4][4], bF[2][4][2];
    auto ldfrag = [&](int pb, uint32_t stg, int ks) {
        const uint32_t ko = (uint32_t)(ks * 32);   // 16 fp16 = 32 B per k-step
#pragma unroll
        for (int mi = 0; mi < 4; ++mi)
            LDSM_X4(aF[pb][mi][0], aF[pb][mi][1], aF[pb][mi][2], aF[pb][mi][3],
                    stg + aoff + (uint32_t)(mi * 16 * ROWB) + ko);
        LDSM_X4(bF[pb][0][0], bF[pb][0][1], bF[pb][1][0], bF[pb][1][1],
                stg + boff + ko);
        LDSM_X4(bF[pb][2][0], bF[pb][2][1], bF[pb][3][0], bF[pb][3][1],
                stg + boff + (uint32_t)(16 * ROWB) + ko);
    };

    for (int kt = 0; kt < KT; ++kt) {
        // after this wait, committed-but-pending must exclude group kt
        if (kt < KT - 1) asm volatile("cp.async.wait_group 1;" ::: "memory");
        else             asm volatile("cp.async.wait_group 0;" ::: "memory");
        __syncthreads();   // stage kt landed for ALL threads; buffer (kt-1)%3 free
        if (kt + 2 < KT) issue(kt + 2, (kt + 2) % 3);

        const uint32_t stg = sb + (kt % 3) * STAGE_BYTES;
        ldfrag(0, stg, 0);
#pragma unroll
        for (int ks = 0; ks < 4; ++ks) {
            const int pb = ks & 1;
            if (ks < 3) ldfrag(pb ^ 1, stg, ks + 1);  // hide LDS under MMAs
#pragma unroll
            for (int mi = 0; mi < 4; ++mi)
#pragma unroll
                for (int ni = 0; ni < 4; ++ni)
                    MMA_F16(acc[mi][ni], aF[pb][mi], bF[pb][ni]);
        }
        // no bottom barrier: buffer kt%3 is only rewritten after the top
        // barrier of iteration kt+1, which all warps reach post-compute.
    }

    // ---- epilogue (D-frag layout identical to tf32 path) ----
#pragma unroll
    for (int mi = 0; mi < 4; ++mi) {
        const int mA = m0 + wm * 64 + mi * 16 + g;
        const int mB = mA + 8;
        if (IS_G1) {
            __half* rowA = g_hbuf + (size_t)(base + mA) * HFF;
            __half* rowB = g_hbuf + (size_t)(base + mB) * HFF;
#pragma unroll
            for (int ni = 0; ni < 4; ++ni) {
                const int col = n0 + wn * 32 + ni * 8 + 2 * tq;
                if (mA < cnt)
                    *(__half2*)(rowA + col) = __floats2half2_rn(
                        gelu_t(acc[mi][ni][0]), gelu_t(acc[mi][ni][1]));
                if (mB < cnt)
                    *(__half2*)(rowB + col) = __floats2half2_rn(
                        gelu_t(acc[mi][ni][2]), gelu_t(acc[mi][ni][3]));
            }
        } else {
            int tokA = 0, tokB = 0;
            float gA = 0.f, gB = 0.f;
            if (mA < cnt) { tokA = g_list[e * T_TOK + mA]; gA = g_gval[e * T_TOK + mA]; }
            if (mB < cnt) { tokB = g_list[e * T_TOK + mB]; gB = g_gval[e * T_TOK + mB]; }
#pragma unroll
            for (int ni = 0; ni < 4; ++ni) {
                const int col = n0 + wn * 32 + ni * 8 + 2 * tq;
                if (mA < cnt) {
                    atomicAdd(&outp[(size_t)tokA * HDIM + col],     gA * acc[mi][ni][0]);
                    atomicAdd(&outp[(size_t)tokA * HDIM + col + 1], gA * acc[mi][ni][1]);
                }
                if (mB < cnt) {
                    atomicAdd(&outp[(size_t)tokB * HDIM + col],     gB * acc[mi][ni][2]);
                    atomicAdd(&outp[(size_t)tokB * HDIM + col + 1], gB * acc[mi][ni][3]);
                }
            }
        }
    }
}

// ---------------- launch ----------------
extern "C" void kernel_launch(void* const* d_in, const int* in_sizes, int n_in,
                              void* d_out, int out_size) {
    const float* x     = (const float*)d_in[0];
    const float* probs = (const float*)d_in[1];
    const void*  idx   = d_in[2];
    const float* W1    = (const float*)d_in[3];
    const float* W2    = (const float*)d_in[4];
    float* out = (float*)d_out;

    cudaFuncSetAttribute(k_gemm<HDIM, true>,
                         cudaFuncAttributeMaxDynamicSharedMemorySize, DYN_SMEM);
    cudaFuncSetAttribute(k_gemm<HFF, false>,
                         cudaFuncAttributeMaxDynamicSharedMemorySize, DYN_SMEM);

    const int n4 = out_size / 4;
    k_zero<<<(n4 + 255) / 256, 256>>>((float4*)out, n4);
    k_detect<<<32, 256>>>((const int*)idx);
    k_gate<<<(T_TOK + 255) / 256, 256>>>(idx, probs);
    k_prepw<<<2048, 256>>>((const float4*)W1, (const float4*)W2);
    k_prepx<<<256, 256>>>((const float4*)x);

    dim3 g1(T_TOK / BM, HFF / BN, NEXP);   // (32, 32, 8); tail CTAs self-prune
    k_gemm<HDIM, true><<<g1, NTHR, DYN_SMEM>>>(nullptr);

    dim3 g2(T_TOK / BM, HDIM / BN, NEXP);  // (32, 8, 8)
    k_gemm<HFF, false><<<g2, NTHR, DYN_SMEM>>>(out);
}